// round 8
// baseline (speedup 1.0000x reference)
#include <cuda_runtime.h>

// Problem constants (fixed shapes from reference)
#define TOK   (4 * 4096)   // B*S = 16384 tokens
#define HDIM  2048
#define TAU   6e-3f        // tier-1 argmax-gap threshold (tf32 fast pass)

// Scratch
__device__ float g_bufA[(size_t)TOK * 1024];  // hid / branch1 stage-2
__device__ float g_bufB[(size_t)TOK * 1024];  // branch1 stage-1
__device__ float g_bufC[(size_t)TOK * 512];   // branch2 stage-1
__device__ float g_bufD[(size_t)TOK * 512];   // branch2 stage-2
__device__ int   g_idx1[TOK];
__device__ int   g_idx2[TOK];
__device__ int   g_idxR[TOK];
__device__ int   g_sel[TOK];
__device__ int   g_cnt[3];   // [0]=branch1, [1]=branch2, [2]=recheck

// ---------------------------------------------------------------------------
// out = h (default for selected==0; branch scatters overwrite). Also zeroes
// the counters (block 0) so no separate init launch is needed.
__global__ void k_prep(const float* __restrict__ h, float* __restrict__ out) {
    if (blockIdx.x == 0 && threadIdx.x < 3) g_cnt[threadIdx.x] = 0;
    int i = blockIdx.x * blockDim.x + threadIdx.x;     // float4 index
    if (i < TOK * (HDIM / 4))
        ((float4*)out)[i] = ((const float4*)h)[i];
}

// ---------------------------------------------------------------------------
// Tier-1: decision from tf32 hid. Near-ties (gap < TAU) go to recheck list.
__global__ void k_sel_fast(const float* __restrict__ hid,   // [TOK,512]
                           const float* __restrict__ W2,    // [3,512]
                           const float* __restrict__ b2) {
    int t = blockIdx.x * blockDim.x + threadIdx.x;
    int tok = t >> 5, lane = t & 31;
    if (tok >= TOK) return;
    const float* hrow = hid + (size_t)tok * 512;
    float s0 = 0.f, s1 = 0.f, s2 = 0.f;
    #pragma unroll 4
    for (int k = lane; k < 512; k += 32) {
        float v = hrow[k];
        s0 += v * W2[k];
        s1 += v * W2[512 + k];
        s2 += v * W2[1024 + k];
    }
    #pragma unroll
    for (int o = 16; o; o >>= 1) {
        s0 += __shfl_down_sync(0xffffffffu, s0, o);
        s1 += __shfl_down_sync(0xffffffffu, s1, o);
        s2 += __shfl_down_sync(0xffffffffu, s2, o);
    }
    if (lane == 0) {
        s0 += b2[0]; s1 += b2[1]; s2 += b2[2];
        int sel = 0; float best = s0;             // first-max rule: strict '>'
        if (s1 > best) { best = s1; sel = 1; }
        if (s2 > best) { best = s2; sel = 2; }
        g_sel[tok] = sel;
        float m1 = fmaxf(s0, fmaxf(s1, s2));
        float mn = fminf(s0, fminf(s1, s2));
        float m2 = s0 + s1 + s2 - m1 - mn;        // second largest
        if (m1 - m2 < TAU) {
            int p = atomicAdd(&g_cnt[2], 1);
            g_idxR[p] = tok;
        }
    }
}

// Tier-2: exact fp32 per-token recompute (one block per flagged token).
// x cached in smem; W1 (4MB) stays L2-resident across blocks. 4 independent
// accumulators break the FFMA dependency chain.
__global__ __launch_bounds__(256)
void k_sel_exact(const float* __restrict__ h,
                 const float* __restrict__ freq,
                 const float* __restrict__ imp,
                 const float* __restrict__ W1,   // [512,2048]
                 const float* __restrict__ b1,
                 const float* __restrict__ W2,   // [3,512]
                 const float* __restrict__ b2) {
    __shared__ float xs[HDIM];
    __shared__ float red[3][256];
    const int tid = threadIdx.x;
    for (int i = blockIdx.x; i < g_cnt[2]; i += gridDim.x) {
        int tok = g_idxR[i];
        float fr = freq[tok], im = imp[tok];
        __syncthreads();
        for (int k = tid; k < HDIM; k += blockDim.x) {
            float s = (k < HDIM / 2) ? fr : im;
            xs[k] = h[(size_t)tok * HDIM + k] * s;
        }
        __syncthreads();
        float p0 = 0.f, p1 = 0.f, p2 = 0.f;
        #pragma unroll
        for (int jj = 0; jj < 2; jj++) {
            int jcol = tid + jj * 256;
            const float4* wrow = (const float4*)(W1 + (size_t)jcol * HDIM);
            float a0 = 0.f, a1 = 0.f, a2 = 0.f, a3 = 0.f;
            #pragma unroll 4
            for (int k4 = 0; k4 < HDIM / 4; k4++) {
                float4 w = wrow[k4];
                float4 x = ((const float4*)xs)[k4];
                a0 = fmaf(w.x, x.x, a0);
                a1 = fmaf(w.y, x.y, a1);
                a2 = fmaf(w.z, x.z, a2);
                a3 = fmaf(w.w, x.w, a3);
            }
            float hj = fmaxf((a0 + a1) + (a2 + a3) + b1[jcol], 0.f);
            p0 = fmaf(hj, W2[jcol], p0);
            p1 = fmaf(hj, W2[512 + jcol], p1);
            p2 = fmaf(hj, W2[1024 + jcol], p2);
        }
        red[0][tid] = p0; red[1][tid] = p1; red[2][tid] = p2;
        __syncthreads();
        for (int s = 128; s; s >>= 1) {
            if (tid < s) {
                red[0][tid] += red[0][tid + s];
                red[1][tid] += red[1][tid + s];
                red[2][tid] += red[2][tid + s];
            }
            __syncthreads();
        }
        if (tid == 0) {
            float s0 = red[0][0] + b2[0];
            float s1 = red[1][0] + b2[1];
            float s2 = red[2][0] + b2[2];
            int sel = 0; float best = s0;
            if (s1 > best) { best = s1; sel = 1; }
            if (s2 > best) { best = s2; sel = 2; }
            g_sel[tok] = sel;
        }
        __syncthreads();
    }
}

// Build branch index lists from final g_sel.
__global__ void k_compact() {
    int tok = blockIdx.x * blockDim.x + threadIdx.x;
    if (tok >= TOK) return;
    int s = g_sel[tok];
    if (s == 1)      { int p = atomicAdd(&g_cnt[0], 1); g_idx1[p] = tok; }
    else if (s == 2) { int p = atomicAdd(&g_cnt[1], 1); g_idx2[p] = tok; }
}

// ---------------------------------------------------------------------------
// tf32 tensor-core NT GEMM, 3-stage cp.async pipeline.
// Tile 128x128, BK=32, 8 warps (2Mx4N), warp tile 64x32, mma.m16n8k8.tf32.
// Smem: 3 stages x (A 128x32 + B 128x32) fp32, XOR-swizzled (granule^row&7).
// MOD: fold per-token freq/imp modulation into A-fragment loads (scale is
// uniform per 32-K chunk since K/2 is a multiple of BK).
// ---------------------------------------------------------------------------
__device__ __forceinline__ void mma_tf32(float (&d)[4], const unsigned (&a)[4],
                                         const unsigned (&b)[2]) {
    asm volatile(
        "mma.sync.aligned.m16n8k8.row.col.f32.tf32.tf32.f32 "
        "{%0,%1,%2,%3}, {%4,%5,%6,%7}, {%8,%9}, {%0,%1,%2,%3};\n"
        : "+f"(d[0]), "+f"(d[1]), "+f"(d[2]), "+f"(d[3])
        : "r"(a[0]), "r"(a[1]), "r"(a[2]), "r"(a[3]), "r"(b[0]), "r"(b[1]));
}

__device__ __forceinline__ void cp16(unsigned dst, const void* src, int nbytes) {
    asm volatile("cp.async.cg.shared.global [%0], [%1], 16, %2;"
                 :: "r"(dst), "l"(src), "r"(nbytes));
}

#define BK   32
#define ASZ  (128 * BK)                    // words per matrix per stage
#define STGW (2 * ASZ)                     // words per stage (A+B)
#define STGB (STGW * 4)                    // bytes per stage
#define TC_SMEM (3 * STGB)                 // 96 KB

template<bool MOD>
__device__ __forceinline__ void gemm_tc_body(
    const float* __restrict__ A, const float* __restrict__ W,
    const float* __restrict__ bias, float* __restrict__ C,
    int M, int K, const int* __restrict__ gather,
    const int* __restrict__ scatter, int ldc, int relu,
    const float* __restrict__ freq, const float* __restrict__ imp,
    int tileM, int tileN)
{
    extern __shared__ float sm[];

    const int tid  = threadIdx.x;
    const int lane = tid & 31;
    const int warp = tid >> 5;
    const int wm0 = (warp >> 2) * 64;
    const int wn0 = (warp & 3) * 32;
    const int g = lane >> 2;           // 0..7
    const int c = lane & 3;            // 0..3

    // Loader mapping: granule j (16B) within row, 4 rows per thread per matrix.
    const int j  = tid & 7;
    const int r0 = tid >> 3;           // 0..31
    const float* asrc[4]; int asz[4];
    const float* bsrc[4];
    unsigned adst[4], bdst[4];
    const unsigned smb = (unsigned)__cvta_generic_to_shared(sm);
    #pragma unroll
    for (int i = 0; i < 4; i++) {
        int r = r0 + 32 * i;           // tile row 0..127
        int m = tileM + r;
        bool v = (m < M);
        int grow = v ? (gather ? gather[m] : m) : 0;
        asrc[i] = A + (size_t)grow * K + j * 4;
        asz[i]  = v ? 16 : 0;          // zfill invalid rows
        bsrc[i] = W + (size_t)(tileN + r) * K + j * 4;
        unsigned woff = r * BK + ((j ^ (r & 7)) << 2);
        adst[i] = smb + woff * 4;
        bdst[i] = smb + (ASZ + woff) * 4;
    }

    // Per-row modulation scales (selector path only). Rows are in-range:
    // selector runs at M = TOK with exact grid.
    float sfr[4][2], sim[4][2];
    if (MOD) {
        #pragma unroll
        for (int mt = 0; mt < 4; mt++) {
            int rA = tileM + wm0 + mt * 16 + g;
            int rB = rA + 8;
            sfr[mt][0] = freq[rA]; sfr[mt][1] = freq[rB];
            sim[mt][0] = imp[rA];  sim[mt][1] = imp[rB];
        }
    }

    float acc[4][4][4];
    #pragma unroll
    for (int mt = 0; mt < 4; mt++)
        #pragma unroll
        for (int nt = 0; nt < 4; nt++)
            #pragma unroll
            for (int q = 0; q < 4; q++) acc[mt][nt][q] = 0.f;

    const int nc = K / BK;

    // Preload stages 0 and 1 (two committed groups)
    #pragma unroll
    for (int i = 0; i < 4; i++) {
        cp16(adst[i], asrc[i], asz[i]);
        cp16(bdst[i], bsrc[i], 16);
    }
    asm volatile("cp.async.commit_group;" ::: "memory");
    if (nc > 1) {
        #pragma unroll
        for (int i = 0; i < 4; i++) {
            cp16(adst[i] + STGB, asrc[i] + BK, asz[i]);
            cp16(bdst[i] + STGB, bsrc[i] + BK, 16);
        }
    }
    asm volatile("cp.async.commit_group;" ::: "memory");

    for (int ch = 0; ch < nc; ch++) {
        // With one (possibly empty) commit per iteration, the group loading
        // chunk ch is always second-from-last here -> wait_group 1 suffices.
        asm volatile("cp.async.wait_group 1;" ::: "memory");
        __syncthreads();

        if (ch + 2 < nc) {
            const int koff = (ch + 2) * BK;
            const unsigned so = ((ch + 2) % 3) * STGB;
            #pragma unroll
            for (int i = 0; i < 4; i++) {
                cp16(adst[i] + so, asrc[i] + koff, asz[i]);
                cp16(bdst[i] + so, bsrc[i] + koff, 16);
            }
        }
        asm volatile("cp.async.commit_group;" ::: "memory");

        const float* As = sm + (ch % 3) * STGW;
        const float* Bs = As + ASZ;
        const bool useFr = MOD && (ch * BK * 2 < K);   // first half of K

        #pragma unroll
        for (int ks = 0; ks < 4; ks++) {
            const int kb2 = ks * 2;            // granule index pair base
            unsigned afr[4][4];
            #pragma unroll
            for (int mt = 0; mt < 4; mt++) {
                int m = wm0 + mt * 16 + g;
                int sw = m & 7;                 // (m+8)&7 == m&7
                int q0 = (kb2 ^ sw) * 4 + c;
                int q1 = ((kb2 + 1) ^ sw) * 4 + c;
                const float* pr0 = As + m * BK;
                const float* pr1 = As + (m + 8) * BK;
                if (MOD) {
                    float s0 = useFr ? sfr[mt][0] : sim[mt][0];
                    float s1 = useFr ? sfr[mt][1] : sim[mt][1];
                    afr[mt][0] = __float_as_uint(pr0[q0] * s0);
                    afr[mt][1] = __float_as_uint(pr1[q0] * s1);
                    afr[mt][2] = __float_as_uint(pr0[q1] * s0);
                    afr[mt][3] = __float_as_uint(pr1[q1] * s1);
                } else {
                    afr[mt][0] = __float_as_uint(pr0[q0]);
                    afr[mt][1] = __float_as_uint(pr1[q0]);
                    afr[mt][2] = __float_as_uint(pr0[q1]);
                    afr[mt][3] = __float_as_uint(pr1[q1]);
                }
            }
            unsigned bfr[4][2];
            #pragma unroll
            for (int nt = 0; nt < 4; nt++) {
                int n = wn0 + nt * 8 + g;
                int sw = n & 7;
                const float* pn = Bs + n * BK;
                bfr[nt][0] = __float_as_uint(pn[(kb2 ^ sw) * 4 + c]);
                bfr[nt][1] = __float_as_uint(pn[((kb2 + 1) ^ sw) * 4 + c]);
            }
            #pragma unroll
            for (int mt = 0; mt < 4; mt++)
                #pragma unroll
                for (int nt = 0; nt < 4; nt++)
                    mma_tf32(acc[mt][nt], afr[mt], bfr[nt]);
        }
    }

    // Epilogue: bias, optional ReLU, optional row scatter. float2 stores.
    #pragma unroll
    for (int mt = 0; mt < 4; mt++) {
        int rowA = tileM + wm0 + mt * 16 + g;
        #pragma unroll
        for (int h2 = 0; h2 < 2; h2++) {
            int r = rowA + 8 * h2;
            if (r >= M) continue;
            int cr = scatter ? scatter[r] : r;
            float* crow = C + (size_t)cr * ldc;
            #pragma unroll
            for (int nt = 0; nt < 4; nt++) {
                int col = tileN + wn0 + nt * 8 + c * 2;
                float2 bb = *(const float2*)(bias + col);
                float2 o;
                o.x = acc[mt][nt][2 * h2 + 0] + bb.x;
                o.y = acc[mt][nt][2 * h2 + 1] + bb.y;
                if (relu) { o.x = fmaxf(o.x, 0.f); o.y = fmaxf(o.y, 0.f); }
                *(float2*)(crow + col) = o;
            }
        }
    }
}

// Selector GEMM: modulation folded in, ReLU, static M = TOK.
__global__ __launch_bounds__(256, 2)
void k_gemm_sel(const float* __restrict__ A, const float* __restrict__ W,
                const float* __restrict__ bias, float* __restrict__ C,
                int K, int ldc,
                const float* __restrict__ freq, const float* __restrict__ imp)
{
    gemm_tc_body<true>(A, W, bias, C, TOK, K, nullptr, nullptr, ldc, 1,
                       freq, imp, blockIdx.y * 128, blockIdx.x * 128);
}

// Dual-branch GEMM: blockIdx.z selects the job (branch1 / branch2).
struct Job {
    const float* A; const float* W; const float* bias; float* C;
    const int* cntp; int K; int N;
    const int* gather; const int* scatter; int ldc;
};

__global__ __launch_bounds__(256, 2)
void k_gemm_dual(Job j0, Job j1)
{
    const Job& j = (blockIdx.z == 0) ? j0 : j1;
    int M = *j.cntp;
    int tileM = blockIdx.y * 128;
    if (tileM >= M) return;
    int tileN = blockIdx.x * 128;
    if (tileN >= j.N) return;
    gemm_tc_body<false>(j.A, j.W, j.bias, j.C, M, j.K, j.gather, j.scatter,
                        j.ldc, 0, nullptr, nullptr, tileM, tileN);
}

// ---------------------------------------------------------------------------
extern "C" void kernel_launch(void* const* d_in, const int* in_sizes, int n_in,
                              void* d_out, int out_size)
{
    const float* h       = (const float*)d_in[0];   // [4,4096,2048]
    const float* freq    = (const float*)d_in[1];   // [4,4096]
    const float* imp     = (const float*)d_in[2];   // [4,4096]
    const float* comp1_W = (const float*)d_in[3];   // [1024,2048]
    const float* comp1_b = (const float*)d_in[4];
    const float* adpt1_W = (const float*)d_in[5];   // [1024,1024]
    const float* adpt1_b = (const float*)d_in[6];
    const float* dec1_W  = (const float*)d_in[7];   // [2048,1024]
    const float* dec1_b  = (const float*)d_in[8];
    const float* comp2_W = (const float*)d_in[9];   // [512,2048]
    const float* comp2_b = (const float*)d_in[10];
    const float* adpt2_W = (const float*)d_in[11];  // [512,512]
    const float* adpt2_b = (const float*)d_in[12];
    const float* dec2_W  = (const float*)d_in[13];  // [2048,512]
    const float* dec2_b  = (const float*)d_in[14];
    const float* sel1_W  = (const float*)d_in[15];  // [512,2048]
    const float* sel1_b  = (const float*)d_in[16];
    const float* sel2_W  = (const float*)d_in[17];  // [3,512]
    const float* sel2_b  = (const float*)d_in[18];
    float* out = (float*)d_out;

    float *bufA, *bufB, *bufC, *bufD; int *idx1, *idx2, *cnt;
    cudaGetSymbolAddress((void**)&bufA, g_bufA);
    cudaGetSymbolAddress((void**)&bufB, g_bufB);
    cudaGetSymbolAddress((void**)&bufC, g_bufC);
    cudaGetSymbolAddress((void**)&bufD, g_bufD);
    cudaGetSymbolAddress((void**)&idx1, g_idx1);
    cudaGetSymbolAddress((void**)&idx2, g_idx2);
    cudaGetSymbolAddress((void**)&cnt,  g_cnt);

    cudaFuncSetAttribute(k_gemm_sel,
        cudaFuncAttributeMaxDynamicSharedMemorySize, TC_SMEM);
    cudaFuncSetAttribute(k_gemm_dual,
        cudaFuncAttributeMaxDynamicSharedMemorySize, TC_SMEM);

    const int MAXY = TOK / 128;  // 128 m-tiles

    // out = h ; counters zeroed by block 0
    {
        int n4 = TOK * HDIM / 4;
        k_prep<<<(n4 + 255) / 256, 256>>>(h, out);
    }

    // selector hidden on tensor cores, modulation fused: bufA [TOK,512]
    k_gemm_sel<<<dim3(512 / 128, MAXY), 256, TC_SMEM>>>(
        h, sel1_W, sel1_b, bufA, HDIM, 512, freq, imp);

    // tier-1: fast argmax + near-tie flagging
    k_sel_fast<<<(TOK * 32 + 255) / 256, 256>>>(bufA, sel2_W, sel2_b);

    // tier-2: exact fp32 per-token recompute for flagged tokens
    k_sel_exact<<<296, 256>>>(h, freq, imp, sel1_W, sel1_b, sel2_W, sel2_b);

    // build branch index lists from final decisions
    k_compact<<<(TOK + 255) / 256, 256>>>();

    // ---- both branches, pairwise-merged GEMMs (z = branch) ----
    {   // compress: b1 h->bufB [n1,1024] ; b2 h->bufC [n2,512]
        Job j0 = {h, comp1_W, comp1_b, bufB, &cnt[0], HDIM, 1024, idx1, nullptr, 1024};
        Job j1 = {h, comp2_W, comp2_b, bufC, &cnt[1], HDIM,  512, idx2, nullptr,  512};
        k_gemm_dual<<<dim3(8, MAXY, 2), 256, TC_SMEM>>>(j0, j1);
    }
    {   // adapt: b1 bufB->bufA ; b2 bufC->bufD
        Job j0 = {bufB, adpt1_W, adpt1_b, bufA, &cnt[0], 1024, 1024, nullptr, nullptr, 1024};
        Job j1 = {bufC, adpt2_W, adpt2_b, bufD, &cnt[1],  512,  512, nullptr, nullptr,  512};
        k_gemm_dual<<<dim3(8, MAXY, 2), 256, TC_SMEM>>>(j0, j1);
    }
    {   // decompress + scatter into out
        Job j0 = {bufA, dec1_W, dec1_b, out, &cnt[0], 1024, HDIM, nullptr, idx1, HDIM};
        Job j1 = {bufD, dec2_W, dec2_b, out, &cnt[1],  512, HDIM, nullptr, idx2, HDIM};
        k_gemm_dual<<<dim3(16, MAXY, 2), 256, TC_SMEM>>>(j0, j1);
    }
}

// round 9
// speedup vs baseline: 1.4783x; 1.4783x over previous
#include <cuda_runtime.h>

// Problem constants (fixed shapes from reference)
#define TOK   (4 * 4096)   // B*S = 16384 tokens
#define HDIM  2048
#define TAU   6e-3f        // tier-1 argmax-gap threshold (tf32 fast pass)
#define RTB   4            // tokens batched per recheck block

// Scratch
__device__ float g_bufA[(size_t)TOK * 1024];  // hid / branch1 stage-2
__device__ float g_bufB[(size_t)TOK * 1024];  // branch1 stage-1
__device__ float g_bufC[(size_t)TOK * 512];   // branch2 stage-1
__device__ float g_bufD[(size_t)TOK * 512];   // branch2 stage-2
__device__ int   g_idx1[TOK];
__device__ int   g_idx2[TOK];
__device__ int   g_idxR[TOK];
__device__ int   g_sel[TOK];
__device__ int   g_cnt[3];   // [0]=branch1, [1]=branch2, [2]=recheck

// ---------------------------------------------------------------------------
// out = h (default for selected==0; branch scatters overwrite). Also zeroes
// the counters (block 0) so no separate init launch is needed.
__global__ void k_prep(const float* __restrict__ h, float* __restrict__ out) {
    if (blockIdx.x == 0 && threadIdx.x < 3) g_cnt[threadIdx.x] = 0;
    int i = blockIdx.x * blockDim.x + threadIdx.x;     // float4 index
    if (i < TOK * (HDIM / 4))
        ((float4*)out)[i] = ((const float4*)h)[i];
}

// ---------------------------------------------------------------------------
// Tier-1: decision from tf32 hid. Near-ties (gap < TAU) go to recheck list.
__global__ void k_sel_fast(const float* __restrict__ hid,   // [TOK,512]
                           const float* __restrict__ W2,    // [3,512]
                           const float* __restrict__ b2) {
    int t = blockIdx.x * blockDim.x + threadIdx.x;
    int tok = t >> 5, lane = t & 31;
    if (tok >= TOK) return;
    const float* hrow = hid + (size_t)tok * 512;
    float s0 = 0.f, s1 = 0.f, s2 = 0.f;
    #pragma unroll 4
    for (int k = lane; k < 512; k += 32) {
        float v = hrow[k];
        s0 += v * W2[k];
        s1 += v * W2[512 + k];
        s2 += v * W2[1024 + k];
    }
    #pragma unroll
    for (int o = 16; o; o >>= 1) {
        s0 += __shfl_down_sync(0xffffffffu, s0, o);
        s1 += __shfl_down_sync(0xffffffffu, s1, o);
        s2 += __shfl_down_sync(0xffffffffu, s2, o);
    }
    if (lane == 0) {
        s0 += b2[0]; s1 += b2[1]; s2 += b2[2];
        int sel = 0; float best = s0;             // first-max rule: strict '>'
        if (s1 > best) { best = s1; sel = 1; }
        if (s2 > best) { best = s2; sel = 2; }
        g_sel[tok] = sel;
        float m1 = fmaxf(s0, fmaxf(s1, s2));
        float mn = fminf(s0, fminf(s1, s2));
        float m2 = s0 + s1 + s2 - m1 - mn;        // second largest
        if (m1 - m2 < TAU) {
            int p = atomicAdd(&g_cnt[2], 1);
            g_idxR[p] = tok;
        }
    }
}

// Tier-2: exact fp32 recompute, RTB tokens per block. Each W1 granule load
// feeds RTB dot products (fixes the L1-wavefront blowup of block-per-token).
// Reductions are fixed-order smem trees -> deterministic across replays.
__global__ __launch_bounds__(256)
void k_sel_exact(const float* __restrict__ h,
                 const float* __restrict__ freq,
                 const float* __restrict__ imp,
                 const float* __restrict__ W1,   // [512,2048]
                 const float* __restrict__ b1,
                 const float* __restrict__ W2,   // [3,512]
                 const float* __restrict__ b2) {
    __shared__ float xs[RTB][HDIM];          // 32 KB
    __shared__ float red[RTB * 3][256];      // 12 KB, fixed-order reduce
    const int tid = threadIdx.x;
    const int nR = g_cnt[2];
    for (int base = blockIdx.x * RTB; base < nR; base += gridDim.x * RTB) {
        const int nt = min(RTB, nR - base);
        __syncthreads();                     // protect xs reuse across iters
        for (int t = 0; t < nt; t++) {
            int tok = g_idxR[base + t];
            float fr = freq[tok], im = imp[tok];
            for (int k = tid; k < HDIM; k += 256) {
                float s = (k < HDIM / 2) ? fr : im;
                xs[t][k] = h[(size_t)tok * HDIM + k] * s;
            }
        }
        __syncthreads();

        float p[RTB][3];
        #pragma unroll
        for (int t = 0; t < RTB; t++)
            p[t][0] = p[t][1] = p[t][2] = 0.f;

        #pragma unroll
        for (int jj = 0; jj < 2; jj++) {
            const int jcol = tid + jj * 256;
            const float4* wrow = (const float4*)(W1 + (size_t)jcol * HDIM);
            float acc[RTB];
            #pragma unroll
            for (int t = 0; t < RTB; t++) acc[t] = 0.f;
            #pragma unroll 4
            for (int k4 = 0; k4 < HDIM / 4; k4++) {
                float4 w = wrow[k4];
                #pragma unroll
                for (int t = 0; t < RTB; t++) {
                    float4 x = ((const float4*)xs[t])[k4];   // LDS broadcast
                    acc[t] = fmaf(w.x, x.x,
                             fmaf(w.y, x.y,
                             fmaf(w.z, x.z,
                             fmaf(w.w, x.w, acc[t]))));
                }
            }
            float bb  = b1[jcol];
            float w20 = W2[jcol], w21 = W2[512 + jcol], w22 = W2[1024 + jcol];
            #pragma unroll
            for (int t = 0; t < RTB; t++) {
                float hj = fmaxf(acc[t] + bb, 0.f);
                p[t][0] = fmaf(hj, w20, p[t][0]);
                p[t][1] = fmaf(hj, w21, p[t][1]);
                p[t][2] = fmaf(hj, w22, p[t][2]);
            }
        }

        #pragma unroll
        for (int t = 0; t < RTB; t++) {
            red[t * 3 + 0][tid] = p[t][0];
            red[t * 3 + 1][tid] = p[t][1];
            red[t * 3 + 2][tid] = p[t][2];
        }
        __syncthreads();
        for (int s = 128; s; s >>= 1) {
            if (tid < s) {
                #pragma unroll
                for (int q = 0; q < RTB * 3; q++)
                    red[q][tid] += red[q][tid + s];
            }
            __syncthreads();
        }
        if (tid < nt) {
            float s0 = red[tid * 3 + 0][0] + b2[0];
            float s1 = red[tid * 3 + 1][0] + b2[1];
            float s2 = red[tid * 3 + 2][0] + b2[2];
            int sel = 0; float best = s0;
            if (s1 > best) { best = s1; sel = 1; }
            if (s2 > best) { best = s2; sel = 2; }
            g_sel[g_idxR[base + tid]] = sel;
        }
    }
}

// Build branch index lists from final g_sel.
__global__ void k_compact() {
    int tok = blockIdx.x * blockDim.x + threadIdx.x;
    if (tok >= TOK) return;
    int s = g_sel[tok];
    if (s == 1)      { int p = atomicAdd(&g_cnt[0], 1); g_idx1[p] = tok; }
    else if (s == 2) { int p = atomicAdd(&g_cnt[1], 1); g_idx2[p] = tok; }
}

// ---------------------------------------------------------------------------
// tf32 tensor-core NT GEMM, 3-stage cp.async pipeline.
// Tile 128x128, BK=32, 8 warps (2Mx4N), warp tile 64x32, mma.m16n8k8.tf32.
// Smem: 3 stages x (A 128x32 + B 128x32) fp32, XOR-swizzled (granule^row&7).
// MOD: fold per-token freq/imp modulation into A-fragment loads (scale is
// uniform per 32-K chunk since K/2 is a multiple of BK).
// ---------------------------------------------------------------------------
__device__ __forceinline__ void mma_tf32(float (&d)[4], const unsigned (&a)[4],
                                         const unsigned (&b)[2]) {
    asm volatile(
        "mma.sync.aligned.m16n8k8.row.col.f32.tf32.tf32.f32 "
        "{%0,%1,%2,%3}, {%4,%5,%6,%7}, {%8,%9}, {%0,%1,%2,%3};\n"
        : "+f"(d[0]), "+f"(d[1]), "+f"(d[2]), "+f"(d[3])
        : "r"(a[0]), "r"(a[1]), "r"(a[2]), "r"(a[3]), "r"(b[0]), "r"(b[1]));
}

__device__ __forceinline__ void cp16(unsigned dst, const void* src, int nbytes) {
    asm volatile("cp.async.cg.shared.global [%0], [%1], 16, %2;"
                 :: "r"(dst), "l"(src), "r"(nbytes));
}

#define BK   32
#define ASZ  (128 * BK)                    // words per matrix per stage
#define STGW (2 * ASZ)                     // words per stage (A+B)
#define STGB (STGW * 4)                    // bytes per stage
#define TC_SMEM (3 * STGB)                 // 96 KB

template<bool MOD>
__device__ __forceinline__ void gemm_tc_body(
    const float* __restrict__ A, const float* __restrict__ W,
    const float* __restrict__ bias, float* __restrict__ C,
    int M, int K, const int* __restrict__ gather,
    const int* __restrict__ scatter, int ldc, int relu,
    const float* __restrict__ freq, const float* __restrict__ imp,
    int tileM, int tileN)
{
    extern __shared__ float sm[];

    const int tid  = threadIdx.x;
    const int lane = tid & 31;
    const int warp = tid >> 5;
    const int wm0 = (warp >> 2) * 64;
    const int wn0 = (warp & 3) * 32;
    const int g = lane >> 2;           // 0..7
    const int c = lane & 3;            // 0..3

    // Loader mapping: granule j (16B) within row, 4 rows per thread per matrix.
    const int j  = tid & 7;
    const int r0 = tid >> 3;           // 0..31
    const float* asrc[4]; int asz[4];
    const float* bsrc[4];
    unsigned adst[4], bdst[4];
    const unsigned smb = (unsigned)__cvta_generic_to_shared(sm);
    #pragma unroll
    for (int i = 0; i < 4; i++) {
        int r = r0 + 32 * i;           // tile row 0..127
        int m = tileM + r;
        bool v = (m < M);
        int grow = v ? (gather ? gather[m] : m) : 0;
        asrc[i] = A + (size_t)grow * K + j * 4;
        asz[i]  = v ? 16 : 0;          // zfill invalid rows
        bsrc[i] = W + (size_t)(tileN + r) * K + j * 4;
        unsigned woff = r * BK + ((j ^ (r & 7)) << 2);
        adst[i] = smb + woff * 4;
        bdst[i] = smb + (ASZ + woff) * 4;
    }

    // Per-row modulation scales (selector path only). Rows are in-range:
    // selector runs at M = TOK with exact grid.
    float sfr[4][2], sim[4][2];
    if (MOD) {
        #pragma unroll
        for (int mt = 0; mt < 4; mt++) {
            int rA = tileM + wm0 + mt * 16 + g;
            int rB = rA + 8;
            sfr[mt][0] = freq[rA]; sfr[mt][1] = freq[rB];
            sim[mt][0] = imp[rA];  sim[mt][1] = imp[rB];
        }
    }

    float acc[4][4][4];
    #pragma unroll
    for (int mt = 0; mt < 4; mt++)
        #pragma unroll
        for (int nt = 0; nt < 4; nt++)
            #pragma unroll
            for (int q = 0; q < 4; q++) acc[mt][nt][q] = 0.f;

    const int nc = K / BK;

    // Preload stages 0 and 1 (two committed groups)
    #pragma unroll
    for (int i = 0; i < 4; i++) {
        cp16(adst[i], asrc[i], asz[i]);
        cp16(bdst[i], bsrc[i], 16);
    }
    asm volatile("cp.async.commit_group;" ::: "memory");
    if (nc > 1) {
        #pragma unroll
        for (int i = 0; i < 4; i++) {
            cp16(adst[i] + STGB, asrc[i] + BK, asz[i]);
            cp16(bdst[i] + STGB, bsrc[i] + BK, 16);
        }
    }
    asm volatile("cp.async.commit_group;" ::: "memory");

    for (int ch = 0; ch < nc; ch++) {
        // With one (possibly empty) commit per iteration, the group loading
        // chunk ch is always second-from-last here -> wait_group 1 suffices.
        asm volatile("cp.async.wait_group 1;" ::: "memory");
        __syncthreads();

        if (ch + 2 < nc) {
            const int koff = (ch + 2) * BK;
            const unsigned so = ((ch + 2) % 3) * STGB;
            #pragma unroll
            for (int i = 0; i < 4; i++) {
                cp16(adst[i] + so, asrc[i] + koff, asz[i]);
                cp16(bdst[i] + so, bsrc[i] + koff, 16);
            }
        }
        asm volatile("cp.async.commit_group;" ::: "memory");

        const float* As = sm + (ch % 3) * STGW;
        const float* Bs = As + ASZ;
        const bool useFr = MOD && (ch * BK * 2 < K);   // first half of K

        #pragma unroll
        for (int ks = 0; ks < 4; ks++) {
            const int kb2 = ks * 2;            // granule index pair base
            unsigned afr[4][4];
            #pragma unroll
            for (int mt = 0; mt < 4; mt++) {
                int m = wm0 + mt * 16 + g;
                int sw = m & 7;                 // (m+8)&7 == m&7
                int q0 = (kb2 ^ sw) * 4 + c;
                int q1 = ((kb2 + 1) ^ sw) * 4 + c;
                const float* pr0 = As + m * BK;
                const float* pr1 = As + (m + 8) * BK;
                if (MOD) {
                    float s0 = useFr ? sfr[mt][0] : sim[mt][0];
                    float s1 = useFr ? sfr[mt][1] : sim[mt][1];
                    afr[mt][0] = __float_as_uint(pr0[q0] * s0);
                    afr[mt][1] = __float_as_uint(pr1[q0] * s1);
                    afr[mt][2] = __float_as_uint(pr0[q1] * s0);
                    afr[mt][3] = __float_as_uint(pr1[q1] * s1);
                } else {
                    afr[mt][0] = __float_as_uint(pr0[q0]);
                    afr[mt][1] = __float_as_uint(pr1[q0]);
                    afr[mt][2] = __float_as_uint(pr0[q1]);
                    afr[mt][3] = __float_as_uint(pr1[q1]);
                }
            }
            unsigned bfr[4][2];
            #pragma unroll
            for (int nt = 0; nt < 4; nt++) {
                int n = wn0 + nt * 8 + g;
                int sw = n & 7;
                const float* pn = Bs + n * BK;
                bfr[nt][0] = __float_as_uint(pn[(kb2 ^ sw) * 4 + c]);
                bfr[nt][1] = __float_as_uint(pn[((kb2 + 1) ^ sw) * 4 + c]);
            }
            #pragma unroll
            for (int mt = 0; mt < 4; mt++)
                #pragma unroll
                for (int nt = 0; nt < 4; nt++)
                    mma_tf32(acc[mt][nt], afr[mt], bfr[nt]);
        }
    }

    // Epilogue: bias, optional ReLU, optional row scatter. float2 stores.
    #pragma unroll
    for (int mt = 0; mt < 4; mt++) {
        int rowA = tileM + wm0 + mt * 16 + g;
        #pragma unroll
        for (int h2 = 0; h2 < 2; h2++) {
            int r = rowA + 8 * h2;
            if (r >= M) continue;
            int cr = scatter ? scatter[r] : r;
            float* crow = C + (size_t)cr * ldc;
            #pragma unroll
            for (int nt = 0; nt < 4; nt++) {
                int col = tileN + wn0 + nt * 8 + c * 2;
                float2 bb = *(const float2*)(bias + col);
                float2 o;
                o.x = acc[mt][nt][2 * h2 + 0] + bb.x;
                o.y = acc[mt][nt][2 * h2 + 1] + bb.y;
                if (relu) { o.x = fmaxf(o.x, 0.f); o.y = fmaxf(o.y, 0.f); }
                *(float2*)(crow + col) = o;
            }
        }
    }
}

// Selector GEMM: modulation folded in, ReLU, static M = TOK.
__global__ __launch_bounds__(256, 2)
void k_gemm_sel(const float* __restrict__ A, const float* __restrict__ W,
                const float* __restrict__ bias, float* __restrict__ C,
                int K, int ldc,
                const float* __restrict__ freq, const float* __restrict__ imp)
{
    gemm_tc_body<true>(A, W, bias, C, TOK, K, nullptr, nullptr, ldc, 1,
                       freq, imp, blockIdx.y * 128, blockIdx.x * 128);
}

// Dual-branch GEMM: blockIdx.z selects the job (branch1 / branch2).
struct Job {
    const float* A; const float* W; const float* bias; float* C;
    const int* cntp; int K; int N;
    const int* gather; const int* scatter; int ldc;
};

__global__ __launch_bounds__(256, 2)
void k_gemm_dual(Job j0, Job j1)
{
    const Job& j = (blockIdx.z == 0) ? j0 : j1;
    int M = *j.cntp;
    int tileM = blockIdx.y * 128;
    if (tileM >= M) return;
    int tileN = blockIdx.x * 128;
    if (tileN >= j.N) return;
    gemm_tc_body<false>(j.A, j.W, j.bias, j.C, M, j.K, j.gather, j.scatter,
                        j.ldc, 0, nullptr, nullptr, tileM, tileN);
}

// ---------------------------------------------------------------------------
extern "C" void kernel_launch(void* const* d_in, const int* in_sizes, int n_in,
                              void* d_out, int out_size)
{
    const float* h       = (const float*)d_in[0];   // [4,4096,2048]
    const float* freq    = (const float*)d_in[1];   // [4,4096]
    const float* imp     = (const float*)d_in[2];   // [4,4096]
    const float* comp1_W = (const float*)d_in[3];   // [1024,2048]
    const float* comp1_b = (const float*)d_in[4];
    const float* adpt1_W = (const float*)d_in[5];   // [1024,1024]
    const float* adpt1_b = (const float*)d_in[6];
    const float* dec1_W  = (const float*)d_in[7];   // [2048,1024]
    const float* dec1_b  = (const float*)d_in[8];
    const float* comp2_W = (const float*)d_in[9];   // [512,2048]
    const float* comp2_b = (const float*)d_in[10];
    const float* adpt2_W = (const float*)d_in[11];  // [512,512]
    const float* adpt2_b = (const float*)d_in[12];
    const float* dec2_W  = (const float*)d_in[13];  // [2048,512]
    const float* dec2_b  = (const float*)d_in[14];
    const float* sel1_W  = (const float*)d_in[15];  // [512,2048]
    const float* sel1_b  = (const float*)d_in[16];
    const float* sel2_W  = (const float*)d_in[17];  // [3,512]
    const float* sel2_b  = (const float*)d_in[18];
    float* out = (float*)d_out;

    float *bufA, *bufB, *bufC, *bufD; int *idx1, *idx2, *cnt;
    cudaGetSymbolAddress((void**)&bufA, g_bufA);
    cudaGetSymbolAddress((void**)&bufB, g_bufB);
    cudaGetSymbolAddress((void**)&bufC, g_bufC);
    cudaGetSymbolAddress((void**)&bufD, g_bufD);
    cudaGetSymbolAddress((void**)&idx1, g_idx1);
    cudaGetSymbolAddress((void**)&idx2, g_idx2);
    cudaGetSymbolAddress((void**)&cnt,  g_cnt);

    cudaFuncSetAttribute(k_gemm_sel,
        cudaFuncAttributeMaxDynamicSharedMemorySize, TC_SMEM);
    cudaFuncSetAttribute(k_gemm_dual,
        cudaFuncAttributeMaxDynamicSharedMemorySize, TC_SMEM);

    const int MAXY = TOK / 128;  // 128 m-tiles

    // out = h ; counters zeroed by block 0
    {
        int n4 = TOK * HDIM / 4;
        k_prep<<<(n4 + 255) / 256, 256>>>(h, out);
    }

    // selector hidden on tensor cores, modulation fused: bufA [TOK,512]
    k_gemm_sel<<<dim3(512 / 128, MAXY), 256, TC_SMEM>>>(
        h, sel1_W, sel1_b, bufA, HDIM, 512, freq, imp);

    // tier-1: fast argmax + near-tie flagging
    k_sel_fast<<<(TOK * 32 + 255) / 256, 256>>>(bufA, sel2_W, sel2_b);

    // tier-2: exact fp32 recheck, RTB tokens per block
    k_sel_exact<<<148, 256>>>(h, freq, imp, sel1_W, sel1_b, sel2_W, sel2_b);

    // build branch index lists from final decisions
    k_compact<<<(TOK + 255) / 256, 256>>>();

    // ---- both branches, pairwise-merged GEMMs (z = branch) ----
    {   // compress: b1 h->bufB [n1,1024] ; b2 h->bufC [n2,512]
        Job j0 = {h, comp1_W, comp1_b, bufB, &cnt[0], HDIM, 1024, idx1, nullptr, 1024};
        Job j1 = {h, comp2_W, comp2_b, bufC, &cnt[1], HDIM,  512, idx2, nullptr,  512};
        k_gemm_dual<<<dim3(8, MAXY, 2), 256, TC_SMEM>>>(j0, j1);
    }
    {   // adapt: b1 bufB->bufA ; b2 bufC->bufD
        Job j0 = {bufB, adpt1_W, adpt1_b, bufA, &cnt[0], 1024, 1024, nullptr, nullptr, 1024};
        Job j1 = {bufC, adpt2_W, adpt2_b, bufD, &cnt[1],  512,  512, nullptr, nullptr,  512};
        k_gemm_dual<<<dim3(8, MAXY, 2), 256, TC_SMEM>>>(j0, j1);
    }
    {   // decompress + scatter into out
        Job j0 = {bufA, dec1_W, dec1_b, out, &cnt[0], 1024, HDIM, nullptr, idx1, HDIM};
        Job j1 = {bufD, dec2_W, dec2_b, out, &cnt[1],  512, HDIM, nullptr, idx2, HDIM};
        k_gemm_dual<<<dim3(16, MAXY, 2), 256, TC_SMEM>>>(j0, j1);
    }
}

// round 10
// speedup vs baseline: 1.6951x; 1.1467x over previous
#include <cuda_runtime.h>

// Problem constants (fixed shapes from reference)
#define TOK   (4 * 4096)   // B*S = 16384 tokens
#define HDIM  2048
#define TAU   6e-3f        // tier-1 argmax-gap threshold (tf32 fast pass)
#define RTB   4            // tokens batched per recheck block

// Scratch
__device__ float g_bufA[(size_t)TOK * 1024];  // hid / branch1 stage-2
__device__ float g_bufB[(size_t)TOK * 1024];  // branch1 stage-1
__device__ float g_bufC[(size_t)TOK * 512];   // branch2 stage-1
__device__ float g_bufD[(size_t)TOK * 512];   // branch2 stage-2
__device__ int   g_idx1[TOK];
__device__ int   g_idx2[TOK];
__device__ int   g_idxR[TOK];
__device__ int   g_sel[TOK];
__device__ int   g_cnt[3];   // [0]=branch1, [1]=branch2, [2]=recheck

// ---------------------------------------------------------------------------
// out = h (default for selected==0; branch scatters overwrite). Also zeroes
// the counters (block 0) so no separate init launch is needed.
__global__ void k_prep(const float* __restrict__ h, float* __restrict__ out) {
    if (blockIdx.x == 0 && threadIdx.x < 3) g_cnt[threadIdx.x] = 0;
    int i = blockIdx.x * blockDim.x + threadIdx.x;     // float4 index
    if (i < TOK * (HDIM / 4))
        ((float4*)out)[i] = ((const float4*)h)[i];
}

// ---------------------------------------------------------------------------
// Tier-1: decision from tf32 hid. Near-ties (gap < TAU) go to recheck list.
__global__ void k_sel_fast(const float* __restrict__ hid,   // [TOK,512]
                           const float* __restrict__ W2,    // [3,512]
                           const float* __restrict__ b2) {
    int t = blockIdx.x * blockDim.x + threadIdx.x;
    int tok = t >> 5, lane = t & 31;
    if (tok >= TOK) return;
    const float* hrow = hid + (size_t)tok * 512;
    float s0 = 0.f, s1 = 0.f, s2 = 0.f;
    #pragma unroll 4
    for (int k = lane; k < 512; k += 32) {
        float v = hrow[k];
        s0 += v * W2[k];
        s1 += v * W2[512 + k];
        s2 += v * W2[1024 + k];
    }
    #pragma unroll
    for (int o = 16; o; o >>= 1) {
        s0 += __shfl_down_sync(0xffffffffu, s0, o);
        s1 += __shfl_down_sync(0xffffffffu, s1, o);
        s2 += __shfl_down_sync(0xffffffffu, s2, o);
    }
    if (lane == 0) {
        s0 += b2[0]; s1 += b2[1]; s2 += b2[2];
        int sel = 0; float best = s0;             // first-max rule: strict '>'
        if (s1 > best) { best = s1; sel = 1; }
        if (s2 > best) { best = s2; sel = 2; }
        g_sel[tok] = sel;
        float m1 = fmaxf(s0, fmaxf(s1, s2));
        float mn = fminf(s0, fminf(s1, s2));
        float m2 = s0 + s1 + s2 - m1 - mn;        // second largest
        if (m1 - m2 < TAU) {
            int p = atomicAdd(&g_cnt[2], 1);
            g_idxR[p] = tok;
        }
    }
}

// Tier-2: exact fp32 recompute, RTB tokens per block.
// Warp-per-jcol-group layout: each warp owns 64 contiguous W1 rows, lanes
// run along k -> every W1 load is fully coalesced (4 wavefronts/LDG.128).
// 4-jcol x RTB-token register tile: 64 FMA per 64B LDS + 64B L1 (balanced).
// All reductions fixed-order (shfl tree + fixed warp order) -> deterministic.
__global__ __launch_bounds__(256)
void k_sel_exact(const float* __restrict__ h,
                 const float* __restrict__ freq,
                 const float* __restrict__ imp,
                 const float* __restrict__ W1,   // [512,2048]
                 const float* __restrict__ b1,
                 const float* __restrict__ W2,   // [3,512]
                 const float* __restrict__ b2) {
    __shared__ float xs[RTB][HDIM];          // 32 KB
    __shared__ float wp[8][RTB][3];          // per-warp logit partials
    const int tid  = threadIdx.x;
    const int lane = tid & 31;
    const int warp = tid >> 5;
    const int nR = g_cnt[2];
    for (int base = blockIdx.x * RTB; base < nR; base += gridDim.x * RTB) {
        const int nt = min(RTB, nR - base);
        __syncthreads();                     // protect xs/wp reuse across iters
        for (int t = 0; t < nt; t++) {
            int tok = g_idxR[base + t];
            float fr = freq[tok], im = imp[tok];
            for (int k = tid; k < HDIM; k += 256) {
                float s = (k < HDIM / 2) ? fr : im;
                xs[t][k] = h[(size_t)tok * HDIM + k] * s;
            }
        }
        // zero unused token slots so their xs reads are defined (results unused)
        for (int t = nt; t < RTB; t++)
            for (int k = tid; k < HDIM; k += 256) xs[t][k] = 0.f;
        __syncthreads();

        float p[RTB][3];
        #pragma unroll
        for (int t = 0; t < RTB; t++)
            p[t][0] = p[t][1] = p[t][2] = 0.f;

        // warp handles jcols [warp*64, warp*64+64), 4 at a time
        for (int grp = 0; grp < 16; grp++) {
            const int jcol0 = warp * 64 + grp * 4;
            const float4* w0 = (const float4*)(W1 + (size_t)(jcol0 + 0) * HDIM);
            const float4* w1 = (const float4*)(W1 + (size_t)(jcol0 + 1) * HDIM);
            const float4* w2 = (const float4*)(W1 + (size_t)(jcol0 + 2) * HDIM);
            const float4* w3 = (const float4*)(W1 + (size_t)(jcol0 + 3) * HDIM);
            float acc[4][RTB];
            #pragma unroll
            for (int jj = 0; jj < 4; jj++)
                #pragma unroll
                for (int t = 0; t < RTB; t++) acc[jj][t] = 0.f;

            for (int q = 0; q < 16; q++) {
                const int k4 = lane + q * 32;          // coalesced
                float4 wv[4] = {w0[k4], w1[k4], w2[k4], w3[k4]};
                float4 xv[RTB];
                #pragma unroll
                for (int t = 0; t < RTB; t++)
                    xv[t] = ((const float4*)xs[t])[k4];
                #pragma unroll
                for (int jj = 0; jj < 4; jj++)
                    #pragma unroll
                    for (int t = 0; t < RTB; t++)
                        acc[jj][t] = fmaf(wv[jj].x, xv[t].x,
                                     fmaf(wv[jj].y, xv[t].y,
                                     fmaf(wv[jj].z, xv[t].z,
                                     fmaf(wv[jj].w, xv[t].w, acc[jj][t]))));
            }
            // fixed shfl tree reduce
            #pragma unroll
            for (int o = 16; o; o >>= 1)
                #pragma unroll
                for (int jj = 0; jj < 4; jj++)
                    #pragma unroll
                    for (int t = 0; t < RTB; t++)
                        acc[jj][t] += __shfl_down_sync(0xffffffffu, acc[jj][t], o);
            if (lane == 0) {
                #pragma unroll
                for (int jj = 0; jj < 4; jj++) {
                    const int jcol = jcol0 + jj;
                    float bb  = b1[jcol];
                    float w20 = W2[jcol], w21 = W2[512 + jcol], w22 = W2[1024 + jcol];
                    #pragma unroll
                    for (int t = 0; t < RTB; t++) {
                        float hj = fmaxf(acc[jj][t] + bb, 0.f);
                        p[t][0] = fmaf(hj, w20, p[t][0]);
                        p[t][1] = fmaf(hj, w21, p[t][1]);
                        p[t][2] = fmaf(hj, w22, p[t][2]);
                    }
                }
            }
        }

        if (lane == 0)
            #pragma unroll
            for (int t = 0; t < RTB; t++) {
                wp[warp][t][0] = p[t][0];
                wp[warp][t][1] = p[t][1];
                wp[warp][t][2] = p[t][2];
            }
        __syncthreads();
        if (tid < nt) {
            // fixed-order sum over warps -> deterministic across replays
            float s0 = b2[0], s1 = b2[1], s2 = b2[2];
            #pragma unroll
            for (int w = 0; w < 8; w++) {
                s0 += wp[w][tid][0];
                s1 += wp[w][tid][1];
                s2 += wp[w][tid][2];
            }
            int sel = 0; float best = s0;
            if (s1 > best) { best = s1; sel = 1; }
            if (s2 > best) { best = s2; sel = 2; }
            g_sel[g_idxR[base + tid]] = sel;
        }
    }
}

// Build branch index lists from final g_sel.
__global__ void k_compact() {
    int tok = blockIdx.x * blockDim.x + threadIdx.x;
    if (tok >= TOK) return;
    int s = g_sel[tok];
    if (s == 1)      { int p = atomicAdd(&g_cnt[0], 1); g_idx1[p] = tok; }
    else if (s == 2) { int p = atomicAdd(&g_cnt[1], 1); g_idx2[p] = tok; }
}

// ---------------------------------------------------------------------------
// tf32 tensor-core NT GEMM, 3-stage cp.async pipeline.
// Tile 128x128, BK=32, 8 warps (2Mx4N), warp tile 64x32, mma.m16n8k8.tf32.
// Smem: 3 stages x (A 128x32 + B 128x32) fp32, XOR-swizzled (granule^row&7).
// MOD: fold per-token freq/imp modulation into A-fragment loads (scale is
// uniform per 32-K chunk since K/2 is a multiple of BK).
// ---------------------------------------------------------------------------
__device__ __forceinline__ void mma_tf32(float (&d)[4], const unsigned (&a)[4],
                                         const unsigned (&b)[2]) {
    asm volatile(
        "mma.sync.aligned.m16n8k8.row.col.f32.tf32.tf32.f32 "
        "{%0,%1,%2,%3}, {%4,%5,%6,%7}, {%8,%9}, {%0,%1,%2,%3};\n"
        : "+f"(d[0]), "+f"(d[1]), "+f"(d[2]), "+f"(d[3])
        : "r"(a[0]), "r"(a[1]), "r"(a[2]), "r"(a[3]), "r"(b[0]), "r"(b[1]));
}

__device__ __forceinline__ void cp16(unsigned dst, const void* src, int nbytes) {
    asm volatile("cp.async.cg.shared.global [%0], [%1], 16, %2;"
                 :: "r"(dst), "l"(src), "r"(nbytes));
}

#define BK   32
#define ASZ  (128 * BK)                    // words per matrix per stage
#define STGW (2 * ASZ)                     // words per stage (A+B)
#define STGB (STGW * 4)                    // bytes per stage
#define TC_SMEM (3 * STGB)                 // 96 KB

template<bool MOD>
__device__ __forceinline__ void gemm_tc_body(
    const float* __restrict__ A, const float* __restrict__ W,
    const float* __restrict__ bias, float* __restrict__ C,
    int M, int K, const int* __restrict__ gather,
    const int* __restrict__ scatter, int ldc, int relu,
    const float* __restrict__ freq, const float* __restrict__ imp,
    int tileM, int tileN)
{
    extern __shared__ float sm[];

    const int tid  = threadIdx.x;
    const int lane = tid & 31;
    const int warp = tid >> 5;
    const int wm0 = (warp >> 2) * 64;
    const int wn0 = (warp & 3) * 32;
    const int g = lane >> 2;           // 0..7
    const int c = lane & 3;            // 0..3

    // Loader mapping: granule j (16B) within row, 4 rows per thread per matrix.
    const int j  = tid & 7;
    const int r0 = tid >> 3;           // 0..31
    const float* asrc[4]; int asz[4];
    const float* bsrc[4];
    unsigned adst[4], bdst[4];
    const unsigned smb = (unsigned)__cvta_generic_to_shared(sm);
    #pragma unroll
    for (int i = 0; i < 4; i++) {
        int r = r0 + 32 * i;           // tile row 0..127
        int m = tileM + r;
        bool v = (m < M);
        int grow = v ? (gather ? gather[m] : m) : 0;
        asrc[i] = A + (size_t)grow * K + j * 4;
        asz[i]  = v ? 16 : 0;          // zfill invalid rows
        bsrc[i] = W + (size_t)(tileN + r) * K + j * 4;
        unsigned woff = r * BK + ((j ^ (r & 7)) << 2);
        adst[i] = smb + woff * 4;
        bdst[i] = smb + (ASZ + woff) * 4;
    }

    // Per-row modulation scales (selector path only). Rows are in-range:
    // selector runs at M = TOK with exact grid.
    float sfr[4][2], sim[4][2];
    if (MOD) {
        #pragma unroll
        for (int mt = 0; mt < 4; mt++) {
            int rA = tileM + wm0 + mt * 16 + g;
            int rB = rA + 8;
            sfr[mt][0] = freq[rA]; sfr[mt][1] = freq[rB];
            sim[mt][0] = imp[rA];  sim[mt][1] = imp[rB];
        }
    }

    float acc[4][4][4];
    #pragma unroll
    for (int mt = 0; mt < 4; mt++)
        #pragma unroll
        for (int nt = 0; nt < 4; nt++)
            #pragma unroll
            for (int q = 0; q < 4; q++) acc[mt][nt][q] = 0.f;

    const int nc = K / BK;

    // Preload stages 0 and 1 (two committed groups)
    #pragma unroll
    for (int i = 0; i < 4; i++) {
        cp16(adst[i], asrc[i], asz[i]);
        cp16(bdst[i], bsrc[i], 16);
    }
    asm volatile("cp.async.commit_group;" ::: "memory");
    if (nc > 1) {
        #pragma unroll
        for (int i = 0; i < 4; i++) {
            cp16(adst[i] + STGB, asrc[i] + BK, asz[i]);
            cp16(bdst[i] + STGB, bsrc[i] + BK, 16);
        }
    }
    asm volatile("cp.async.commit_group;" ::: "memory");

    for (int ch = 0; ch < nc; ch++) {
        // With one (possibly empty) commit per iteration, the group loading
        // chunk ch is always second-from-last here -> wait_group 1 suffices.
        asm volatile("cp.async.wait_group 1;" ::: "memory");
        __syncthreads();

        if (ch + 2 < nc) {
            const int koff = (ch + 2) * BK;
            const unsigned so = ((ch + 2) % 3) * STGB;
            #pragma unroll
            for (int i = 0; i < 4; i++) {
                cp16(adst[i] + so, asrc[i] + koff, asz[i]);
                cp16(bdst[i] + so, bsrc[i] + koff, 16);
            }
        }
        asm volatile("cp.async.commit_group;" ::: "memory");

        const float* As = sm + (ch % 3) * STGW;
        const float* Bs = As + ASZ;
        const bool useFr = MOD && (ch * BK * 2 < K);   // first half of K

        #pragma unroll
        for (int ks = 0; ks < 4; ks++) {
            const int kb2 = ks * 2;            // granule index pair base
            unsigned afr[4][4];
            #pragma unroll
            for (int mt = 0; mt < 4; mt++) {
                int m = wm0 + mt * 16 + g;
                int sw = m & 7;                 // (m+8)&7 == m&7
                int q0 = (kb2 ^ sw) * 4 + c;
                int q1 = ((kb2 + 1) ^ sw) * 4 + c;
                const float* pr0 = As + m * BK;
                const float* pr1 = As + (m + 8) * BK;
                if (MOD) {
                    float s0 = useFr ? sfr[mt][0] : sim[mt][0];
                    float s1 = useFr ? sfr[mt][1] : sim[mt][1];
                    afr[mt][0] = __float_as_uint(pr0[q0] * s0);
                    afr[mt][1] = __float_as_uint(pr1[q0] * s1);
                    afr[mt][2] = __float_as_uint(pr0[q1] * s0);
                    afr[mt][3] = __float_as_uint(pr1[q1] * s1);
                } else {
                    afr[mt][0] = __float_as_uint(pr0[q0]);
                    afr[mt][1] = __float_as_uint(pr1[q0]);
                    afr[mt][2] = __float_as_uint(pr0[q1]);
                    afr[mt][3] = __float_as_uint(pr1[q1]);
                }
            }
            unsigned bfr[4][2];
            #pragma unroll
            for (int nt = 0; nt < 4; nt++) {
                int n = wn0 + nt * 8 + g;
                int sw = n & 7;
                const float* pn = Bs + n * BK;
                bfr[nt][0] = __float_as_uint(pn[(kb2 ^ sw) * 4 + c]);
                bfr[nt][1] = __float_as_uint(pn[((kb2 + 1) ^ sw) * 4 + c]);
            }
            #pragma unroll
            for (int mt = 0; mt < 4; mt++)
                #pragma unroll
                for (int nt = 0; nt < 4; nt++)
                    mma_tf32(acc[mt][nt], afr[mt], bfr[nt]);
        }
    }

    // Epilogue: bias, optional ReLU, optional row scatter. float2 stores.
    #pragma unroll
    for (int mt = 0; mt < 4; mt++) {
        int rowA = tileM + wm0 + mt * 16 + g;
        #pragma unroll
        for (int h2 = 0; h2 < 2; h2++) {
            int r = rowA + 8 * h2;
            if (r >= M) continue;
            int cr = scatter ? scatter[r] : r;
            float* crow = C + (size_t)cr * ldc;
            #pragma unroll
            for (int nt = 0; nt < 4; nt++) {
                int col = tileN + wn0 + nt * 8 + c * 2;
                float2 bb = *(const float2*)(bias + col);
                float2 o;
                o.x = acc[mt][nt][2 * h2 + 0] + bb.x;
                o.y = acc[mt][nt][2 * h2 + 1] + bb.y;
                if (relu) { o.x = fmaxf(o.x, 0.f); o.y = fmaxf(o.y, 0.f); }
                *(float2*)(crow + col) = o;
            }
        }
    }
}

// Selector GEMM: modulation folded in, ReLU, static M = TOK.
__global__ __launch_bounds__(256, 2)
void k_gemm_sel(const float* __restrict__ A, const float* __restrict__ W,
                const float* __restrict__ bias, float* __restrict__ C,
                int K, int ldc,
                const float* __restrict__ freq, const float* __restrict__ imp)
{
    gemm_tc_body<true>(A, W, bias, C, TOK, K, nullptr, nullptr, ldc, 1,
                       freq, imp, blockIdx.y * 128, blockIdx.x * 128);
}

// Dual-branch GEMM: blockIdx.z selects the job (branch1 / branch2).
struct Job {
    const float* A; const float* W; const float* bias; float* C;
    const int* cntp; int K; int N;
    const int* gather; const int* scatter; int ldc;
};

__global__ __launch_bounds__(256, 2)
void k_gemm_dual(Job j0, Job j1)
{
    const Job& j = (blockIdx.z == 0) ? j0 : j1;
    int M = *j.cntp;
    int tileM = blockIdx.y * 128;
    if (tileM >= M) return;
    int tileN = blockIdx.x * 128;
    if (tileN >= j.N) return;
    gemm_tc_body<false>(j.A, j.W, j.bias, j.C, M, j.K, j.gather, j.scatter,
                        j.ldc, 0, nullptr, nullptr, tileM, tileN);
}

// ---------------------------------------------------------------------------
extern "C" void kernel_launch(void* const* d_in, const int* in_sizes, int n_in,
                              void* d_out, int out_size)
{
    const float* h       = (const float*)d_in[0];   // [4,4096,2048]
    const float* freq    = (const float*)d_in[1];   // [4,4096]
    const float* imp     = (const float*)d_in[2];   // [4,4096]
    const float* comp1_W = (const float*)d_in[3];   // [1024,2048]
    const float* comp1_b = (const float*)d_in[4];
    const float* adpt1_W = (const float*)d_in[5];   // [1024,1024]
    const float* adpt1_b = (const float*)d_in[6];
    const float* dec1_W  = (const float*)d_in[7];   // [2048,1024]
    const float* dec1_b  = (const float*)d_in[8];
    const float* comp2_W = (const float*)d_in[9];   // [512,2048]
    const float* comp2_b = (const float*)d_in[10];
    const float* adpt2_W = (const float*)d_in[11];  // [512,512]
    const float* adpt2_b = (const float*)d_in[12];
    const float* dec2_W  = (const float*)d_in[13];  // [2048,512]
    const float* dec2_b  = (const float*)d_in[14];
    const float* sel1_W  = (const float*)d_in[15];  // [512,2048]
    const float* sel1_b  = (const float*)d_in[16];
    const float* sel2_W  = (const float*)d_in[17];  // [3,512]
    const float* sel2_b  = (const float*)d_in[18];
    float* out = (float*)d_out;

    float *bufA, *bufB, *bufC, *bufD; int *idx1, *idx2, *cnt;
    cudaGetSymbolAddress((void**)&bufA, g_bufA);
    cudaGetSymbolAddress((void**)&bufB, g_bufB);
    cudaGetSymbolAddress((void**)&bufC, g_bufC);
    cudaGetSymbolAddress((void**)&bufD, g_bufD);
    cudaGetSymbolAddress((void**)&idx1, g_idx1);
    cudaGetSymbolAddress((void**)&idx2, g_idx2);
    cudaGetSymbolAddress((void**)&cnt,  g_cnt);

    cudaFuncSetAttribute(k_gemm_sel,
        cudaFuncAttributeMaxDynamicSharedMemorySize, TC_SMEM);
    cudaFuncSetAttribute(k_gemm_dual,
        cudaFuncAttributeMaxDynamicSharedMemorySize, TC_SMEM);

    const int MAXY = TOK / 128;  // 128 m-tiles

    // out = h ; counters zeroed by block 0
    {
        int n4 = TOK * HDIM / 4;
        k_prep<<<(n4 + 255) / 256, 256>>>(h, out);
    }

    // selector hidden on tensor cores, modulation fused: bufA [TOK,512]
    k_gemm_sel<<<dim3(512 / 128, MAXY), 256, TC_SMEM>>>(
        h, sel1_W, sel1_b, bufA, HDIM, 512, freq, imp);

    // tier-1: fast argmax + near-tie flagging
    k_sel_fast<<<(TOK * 32 + 255) / 256, 256>>>(bufA, sel2_W, sel2_b);

    // tier-2: exact fp32 recheck, coalesced warp-per-jcol-group
    k_sel_exact<<<148, 256>>>(h, freq, imp, sel1_W, sel1_b, sel2_W, sel2_b);

    // build branch index lists from final decisions
    k_compact<<<(TOK + 255) / 256, 256>>>();

    // ---- both branches, pairwise-merged GEMMs (z = branch) ----
    {   // compress: b1 h->bufB [n1,1024] ; b2 h->bufC [n2,512]
        Job j0 = {h, comp1_W, comp1_b, bufB, &cnt[0], HDIM, 1024, idx1, nullptr, 1024};
        Job j1 = {h, comp2_W, comp2_b, bufC, &cnt[1], HDIM,  512, idx2, nullptr,  512};
        k_gemm_dual<<<dim3(8, MAXY, 2), 256, TC_SMEM>>>(j0, j1);
    }
    {   // adapt: b1 bufB->bufA ; b2 bufC->bufD
        Job j0 = {bufB, adpt1_W, adpt1_b, bufA, &cnt[0], 1024, 1024, nullptr, nullptr, 1024};
        Job j1 = {bufC, adpt2_W, adpt2_b, bufD, &cnt[1],  512,  512, nullptr, nullptr,  512};
        k_gemm_dual<<<dim3(8, MAXY, 2), 256, TC_SMEM>>>(j0, j1);
    }
    {   // decompress + scatter into out
        Job j0 = {bufA, dec1_W, dec1_b, out, &cnt[0], 1024, HDIM, nullptr, idx1, HDIM};
        Job j1 = {bufD, dec2_W, dec2_b, out, &cnt[1],  512, HDIM, nullptr, idx2, HDIM};
        k_gemm_dual<<<dim3(16, MAXY, 2), 256, TC_SMEM>>>(j0, j1);
    }
}

// round 11
// speedup vs baseline: 1.8311x; 1.0802x over previous
#include <cuda_runtime.h>

// Problem constants (fixed shapes from reference)
#define TOK   (4 * 4096)   // B*S = 16384 tokens
#define HDIM  2048
#define TAU   6e-3f        // tier-1 argmax-gap threshold (tf32 fast pass)
#define RTB   4            // tokens batched per recheck block

// Scratch
__device__ float g_bufA[(size_t)TOK * 1024];  // hid / branch1 stage-2
__device__ float g_bufB[(size_t)TOK * 1024];  // branch1 stage-1
__device__ float g_bufC[(size_t)TOK * 512];   // branch2 stage-1
__device__ float g_bufD[(size_t)TOK * 512];   // branch2 stage-2
__device__ float g_part[TOK][4][3];           // recheck partial logits
__device__ int   g_idx1[TOK];
__device__ int   g_idx2[TOK];
__device__ int   g_idxR[TOK];
__device__ int   g_sel[TOK];
__device__ int   g_cnt[3];   // [0]=branch1, [1]=branch2, [2]=recheck

// ---------------------------------------------------------------------------
// out = h (default for selected==0; branch scatters overwrite). Also zeroes
// the counters (block 0) so no separate init launch is needed.
__global__ void k_prep(const float* __restrict__ h, float* __restrict__ out) {
    if (blockIdx.x == 0 && threadIdx.x < 3) g_cnt[threadIdx.x] = 0;
    int i = blockIdx.x * blockDim.x + threadIdx.x;     // float4 index
    if (i < TOK * (HDIM / 4))
        ((float4*)out)[i] = ((const float4*)h)[i];
}

// ---------------------------------------------------------------------------
// Tier-1: decision from tf32 hid. Near-ties (gap < TAU) go to recheck list.
__global__ void k_sel_fast(const float* __restrict__ hid,   // [TOK,512]
                           const float* __restrict__ W2,    // [3,512]
                           const float* __restrict__ b2) {
    int t = blockIdx.x * blockDim.x + threadIdx.x;
    int tok = t >> 5, lane = t & 31;
    if (tok >= TOK) return;
    const float* hrow = hid + (size_t)tok * 512;
    float s0 = 0.f, s1 = 0.f, s2 = 0.f;
    #pragma unroll 4
    for (int k = lane; k < 512; k += 32) {
        float v = hrow[k];
        s0 += v * W2[k];
        s1 += v * W2[512 + k];
        s2 += v * W2[1024 + k];
    }
    #pragma unroll
    for (int o = 16; o; o >>= 1) {
        s0 += __shfl_down_sync(0xffffffffu, s0, o);
        s1 += __shfl_down_sync(0xffffffffu, s1, o);
        s2 += __shfl_down_sync(0xffffffffu, s2, o);
    }
    if (lane == 0) {
        s0 += b2[0]; s1 += b2[1]; s2 += b2[2];
        int sel = 0; float best = s0;             // first-max rule: strict '>'
        if (s1 > best) { best = s1; sel = 1; }
        if (s2 > best) { best = s2; sel = 2; }
        g_sel[tok] = sel;
        float m1 = fmaxf(s0, fmaxf(s1, s2));
        float mn = fminf(s0, fminf(s1, s2));
        float m2 = s0 + s1 + s2 - m1 - mn;        // second largest
        if (m1 - m2 < TAU) {
            int p = atomicAdd(&g_cnt[2], 1);
            g_idxR[p] = tok;
        }
    }
}

// Tier-2: exact fp32 recompute, RTB tokens per block, jcol-quartered across
// blockIdx.y (4x blocks -> 4 CTAs/SM -> latency hidden). Each block computes
// partial logits over its 128 jcols; k_sel_fin combines quarters in fixed
// order. Coalesced W1 loads (lanes along k); fixed shfl/warp-order reduces.
__global__ __launch_bounds__(256)
void k_sel_exact(const float* __restrict__ h,
                 const float* __restrict__ freq,
                 const float* __restrict__ imp,
                 const float* __restrict__ W1,   // [512,2048]
                 const float* __restrict__ b1,
                 const float* __restrict__ W2)   // [3,512]
{
    __shared__ float xs[RTB][HDIM];          // 32 KB
    __shared__ float wp[8][RTB][3];          // per-warp logit partials
    const int tid  = threadIdx.x;
    const int lane = tid & 31;
    const int warp = tid >> 5;
    const int qy   = blockIdx.y;             // jcol quarter 0..3
    const int nR = g_cnt[2];
    for (int base = blockIdx.x * RTB; base < nR; base += gridDim.x * RTB) {
        const int nt = min(RTB, nR - base);
        __syncthreads();                     // protect xs/wp reuse across iters
        for (int t = 0; t < nt; t++) {
            int tok = g_idxR[base + t];
            float fr = freq[tok], im = imp[tok];
            for (int k = tid; k < HDIM; k += 256) {
                float s = (k < HDIM / 2) ? fr : im;
                xs[t][k] = h[(size_t)tok * HDIM + k] * s;
            }
        }
        // zero unused token slots so their xs reads are defined (results unused)
        for (int t = nt; t < RTB; t++)
            for (int k = tid; k < HDIM; k += 256) xs[t][k] = 0.f;
        __syncthreads();

        float p[RTB][3];
        #pragma unroll
        for (int t = 0; t < RTB; t++)
            p[t][0] = p[t][1] = p[t][2] = 0.f;

        // this block: jcols [qy*128, qy*128+128); warp handles 16, 4 at a time
        #pragma unroll
        for (int grp = 0; grp < 4; grp++) {
            const int jcol0 = qy * 128 + warp * 16 + grp * 4;
            const float4* w0 = (const float4*)(W1 + (size_t)(jcol0 + 0) * HDIM);
            const float4* w1 = (const float4*)(W1 + (size_t)(jcol0 + 1) * HDIM);
            const float4* w2 = (const float4*)(W1 + (size_t)(jcol0 + 2) * HDIM);
            const float4* w3 = (const float4*)(W1 + (size_t)(jcol0 + 3) * HDIM);
            float acc[4][RTB];
            #pragma unroll
            for (int jj = 0; jj < 4; jj++)
                #pragma unroll
                for (int t = 0; t < RTB; t++) acc[jj][t] = 0.f;

            #pragma unroll 2
            for (int q = 0; q < 16; q++) {
                const int k4 = lane + q * 32;          // coalesced
                float4 wv[4] = {w0[k4], w1[k4], w2[k4], w3[k4]};
                float4 xv[RTB];
                #pragma unroll
                for (int t = 0; t < RTB; t++)
                    xv[t] = ((const float4*)xs[t])[k4];
                #pragma unroll
                for (int jj = 0; jj < 4; jj++)
                    #pragma unroll
                    for (int t = 0; t < RTB; t++)
                        acc[jj][t] = fmaf(wv[jj].x, xv[t].x,
                                     fmaf(wv[jj].y, xv[t].y,
                                     fmaf(wv[jj].z, xv[t].z,
                                     fmaf(wv[jj].w, xv[t].w, acc[jj][t]))));
            }
            // fixed shfl tree reduce
            #pragma unroll
            for (int o = 16; o; o >>= 1)
                #pragma unroll
                for (int jj = 0; jj < 4; jj++)
                    #pragma unroll
                    for (int t = 0; t < RTB; t++)
                        acc[jj][t] += __shfl_down_sync(0xffffffffu, acc[jj][t], o);
            if (lane == 0) {
                #pragma unroll
                for (int jj = 0; jj < 4; jj++) {
                    const int jcol = jcol0 + jj;
                    float bb  = b1[jcol];
                    float w20 = W2[jcol], w21 = W2[512 + jcol], w22 = W2[1024 + jcol];
                    #pragma unroll
                    for (int t = 0; t < RTB; t++) {
                        float hj = fmaxf(acc[jj][t] + bb, 0.f);
                        p[t][0] = fmaf(hj, w20, p[t][0]);
                        p[t][1] = fmaf(hj, w21, p[t][1]);
                        p[t][2] = fmaf(hj, w22, p[t][2]);
                    }
                }
            }
        }

        if (lane == 0)
            #pragma unroll
            for (int t = 0; t < RTB; t++) {
                wp[warp][t][0] = p[t][0];
                wp[warp][t][1] = p[t][1];
                wp[warp][t][2] = p[t][2];
            }
        __syncthreads();
        if (tid < nt) {
            // fixed-order sum over warps -> deterministic across replays
            float s0 = 0.f, s1 = 0.f, s2 = 0.f;
            #pragma unroll
            for (int w = 0; w < 8; w++) {
                s0 += wp[w][tid][0];
                s1 += wp[w][tid][1];
                s2 += wp[w][tid][2];
            }
            g_part[base + tid][qy][0] = s0;
            g_part[base + tid][qy][1] = s1;
            g_part[base + tid][qy][2] = s2;
        }
    }
}

// Combine the 4 jcol-quarters (fixed order), decide, write g_sel.
__global__ void k_sel_fin(const float* __restrict__ b2) {
    int r = blockIdx.x * blockDim.x + threadIdx.x;
    if (r >= g_cnt[2]) return;
    float s0 = b2[0], s1 = b2[1], s2 = b2[2];
    #pragma unroll
    for (int q = 0; q < 4; q++) {
        s0 += g_part[r][q][0];
        s1 += g_part[r][q][1];
        s2 += g_part[r][q][2];
    }
    int sel = 0; float best = s0;
    if (s1 > best) { best = s1; sel = 1; }
    if (s2 > best) { best = s2; sel = 2; }
    g_sel[g_idxR[r]] = sel;
}

// Build branch index lists from final g_sel.
__global__ void k_compact() {
    int tok = blockIdx.x * blockDim.x + threadIdx.x;
    if (tok >= TOK) return;
    int s = g_sel[tok];
    if (s == 1)      { int p = atomicAdd(&g_cnt[0], 1); g_idx1[p] = tok; }
    else if (s == 2) { int p = atomicAdd(&g_cnt[1], 1); g_idx2[p] = tok; }
}

// ---------------------------------------------------------------------------
// tf32 tensor-core NT GEMM, 3-stage cp.async pipeline.
// Tile 128x128, BK=32, 8 warps (2Mx4N), warp tile 64x32, mma.m16n8k8.tf32.
// Smem: 3 stages x (A 128x32 + B 128x32) fp32, XOR-swizzled (granule^row&7).
// MOD: fold per-token freq/imp modulation into A-fragment loads (scale is
// uniform per 32-K chunk since K/2 is a multiple of BK).
// ---------------------------------------------------------------------------
__device__ __forceinline__ void mma_tf32(float (&d)[4], const unsigned (&a)[4],
                                         const unsigned (&b)[2]) {
    asm volatile(
        "mma.sync.aligned.m16n8k8.row.col.f32.tf32.tf32.f32 "
        "{%0,%1,%2,%3}, {%4,%5,%6,%7}, {%8,%9}, {%0,%1,%2,%3};\n"
        : "+f"(d[0]), "+f"(d[1]), "+f"(d[2]), "+f"(d[3])
        : "r"(a[0]), "r"(a[1]), "r"(a[2]), "r"(a[3]), "r"(b[0]), "r"(b[1]));
}

__device__ __forceinline__ void cp16(unsigned dst, const void* src, int nbytes) {
    asm volatile("cp.async.cg.shared.global [%0], [%1], 16, %2;"
                 :: "r"(dst), "l"(src), "r"(nbytes));
}

#define BK   32
#define ASZ  (128 * BK)                    // words per matrix per stage
#define STGW (2 * ASZ)                     // words per stage (A+B)
#define STGB (STGW * 4)                    // bytes per stage
#define TC_SMEM (3 * STGB)                 // 96 KB

template<bool MOD>
__device__ __forceinline__ void gemm_tc_body(
    const float* __restrict__ A, const float* __restrict__ W,
    const float* __restrict__ bias, float* __restrict__ C,
    int M, int K, const int* __restrict__ gather,
    const int* __restrict__ scatter, int ldc, int relu,
    const float* __restrict__ freq, const float* __restrict__ imp,
    int tileM, int tileN)
{
    extern __shared__ float sm[];

    const int tid  = threadIdx.x;
    const int lane = tid & 31;
    const int warp = tid >> 5;
    const int wm0 = (warp >> 2) * 64;
    const int wn0 = (warp & 3) * 32;
    const int g = lane >> 2;           // 0..7
    const int c = lane & 3;            // 0..3

    // Loader mapping: granule j (16B) within row, 4 rows per thread per matrix.
    const int j  = tid & 7;
    const int r0 = tid >> 3;           // 0..31
    const float* asrc[4]; int asz[4];
    const float* bsrc[4];
    unsigned adst[4], bdst[4];
    const unsigned smb = (unsigned)__cvta_generic_to_shared(sm);
    #pragma unroll
    for (int i = 0; i < 4; i++) {
        int r = r0 + 32 * i;           // tile row 0..127
        int m = tileM + r;
        bool v = (m < M);
        int grow = v ? (gather ? gather[m] : m) : 0;
        asrc[i] = A + (size_t)grow * K + j * 4;
        asz[i]  = v ? 16 : 0;          // zfill invalid rows
        bsrc[i] = W + (size_t)(tileN + r) * K + j * 4;
        unsigned woff = r * BK + ((j ^ (r & 7)) << 2);
        adst[i] = smb + woff * 4;
        bdst[i] = smb + (ASZ + woff) * 4;
    }

    // Per-row modulation scales (selector path only). Rows are in-range:
    // selector runs at M = TOK with exact grid.
    float sfr[4][2], sim[4][2];
    if (MOD) {
        #pragma unroll
        for (int mt = 0; mt < 4; mt++) {
            int rA = tileM + wm0 + mt * 16 + g;
            int rB = rA + 8;
            sfr[mt][0] = freq[rA]; sfr[mt][1] = freq[rB];
            sim[mt][0] = imp[rA];  sim[mt][1] = imp[rB];
        }
    }

    float acc[4][4][4];
    #pragma unroll
    for (int mt = 0; mt < 4; mt++)
        #pragma unroll
        for (int nt = 0; nt < 4; nt++)
            #pragma unroll
            for (int q = 0; q < 4; q++) acc[mt][nt][q] = 0.f;

    const int nc = K / BK;

    // Preload stages 0 and 1 (two committed groups)
    #pragma unroll
    for (int i = 0; i < 4; i++) {
        cp16(adst[i], asrc[i], asz[i]);
        cp16(bdst[i], bsrc[i], 16);
    }
    asm volatile("cp.async.commit_group;" ::: "memory");
    if (nc > 1) {
        #pragma unroll
        for (int i = 0; i < 4; i++) {
            cp16(adst[i] + STGB, asrc[i] + BK, asz[i]);
            cp16(bdst[i] + STGB, bsrc[i] + BK, 16);
        }
    }
    asm volatile("cp.async.commit_group;" ::: "memory");

    for (int ch = 0; ch < nc; ch++) {
        // With one (possibly empty) commit per iteration, the group loading
        // chunk ch is always second-from-last here -> wait_group 1 suffices.
        asm volatile("cp.async.wait_group 1;" ::: "memory");
        __syncthreads();

        if (ch + 2 < nc) {
            const int koff = (ch + 2) * BK;
            const unsigned so = ((ch + 2) % 3) * STGB;
            #pragma unroll
            for (int i = 0; i < 4; i++) {
                cp16(adst[i] + so, asrc[i] + koff, asz[i]);
                cp16(bdst[i] + so, bsrc[i] + koff, 16);
            }
        }
        asm volatile("cp.async.commit_group;" ::: "memory");

        const float* As = sm + (ch % 3) * STGW;
        const float* Bs = As + ASZ;
        const bool useFr = MOD && (ch * BK * 2 < K);   // first half of K

        #pragma unroll
        for (int ks = 0; ks < 4; ks++) {
            const int kb2 = ks * 2;            // granule index pair base
            unsigned afr[4][4];
            #pragma unroll
            for (int mt = 0; mt < 4; mt++) {
                int m = wm0 + mt * 16 + g;
                int sw = m & 7;                 // (m+8)&7 == m&7
                int q0 = (kb2 ^ sw) * 4 + c;
                int q1 = ((kb2 + 1) ^ sw) * 4 + c;
                const float* pr0 = As + m * BK;
                const float* pr1 = As + (m + 8) * BK;
                if (MOD) {
                    float s0 = useFr ? sfr[mt][0] : sim[mt][0];
                    float s1 = useFr ? sfr[mt][1] : sim[mt][1];
                    afr[mt][0] = __float_as_uint(pr0[q0] * s0);
                    afr[mt][1] = __float_as_uint(pr1[q0] * s1);
                    afr[mt][2] = __float_as_uint(pr0[q1] * s0);
                    afr[mt][3] = __float_as_uint(pr1[q1] * s1);
                } else {
                    afr[mt][0] = __float_as_uint(pr0[q0]);
                    afr[mt][1] = __float_as_uint(pr1[q0]);
                    afr[mt][2] = __float_as_uint(pr0[q1]);
                    afr[mt][3] = __float_as_uint(pr1[q1]);
                }
            }
            unsigned bfr[4][2];
            #pragma unroll
            for (int nt = 0; nt < 4; nt++) {
                int n = wn0 + nt * 8 + g;
                int sw = n & 7;
                const float* pn = Bs + n * BK;
                bfr[nt][0] = __float_as_uint(pn[(kb2 ^ sw) * 4 + c]);
                bfr[nt][1] = __float_as_uint(pn[((kb2 + 1) ^ sw) * 4 + c]);
            }
            #pragma unroll
            for (int mt = 0; mt < 4; mt++)
                #pragma unroll
                for (int nt = 0; nt < 4; nt++)
                    mma_tf32(acc[mt][nt], afr[mt], bfr[nt]);
        }
    }

    // Epilogue: bias, optional ReLU, optional row scatter. float2 stores.
    #pragma unroll
    for (int mt = 0; mt < 4; mt++) {
        int rowA = tileM + wm0 + mt * 16 + g;
        #pragma unroll
        for (int h2 = 0; h2 < 2; h2++) {
            int r = rowA + 8 * h2;
            if (r >= M) continue;
            int cr = scatter ? scatter[r] : r;
            float* crow = C + (size_t)cr * ldc;
            #pragma unroll
            for (int nt = 0; nt < 4; nt++) {
                int col = tileN + wn0 + nt * 8 + c * 2;
                float2 bb = *(const float2*)(bias + col);
                float2 o;
                o.x = acc[mt][nt][2 * h2 + 0] + bb.x;
                o.y = acc[mt][nt][2 * h2 + 1] + bb.y;
                if (relu) { o.x = fmaxf(o.x, 0.f); o.y = fmaxf(o.y, 0.f); }
                *(float2*)(crow + col) = o;
            }
        }
    }
}

// Selector GEMM: modulation folded in, ReLU, static M = TOK.
__global__ __launch_bounds__(256, 2)
void k_gemm_sel(const float* __restrict__ A, const float* __restrict__ W,
                const float* __restrict__ bias, float* __restrict__ C,
                int K, int ldc,
                const float* __restrict__ freq, const float* __restrict__ imp)
{
    gemm_tc_body<true>(A, W, bias, C, TOK, K, nullptr, nullptr, ldc, 1,
                       freq, imp, blockIdx.y * 128, blockIdx.x * 128);
}

// Dual-branch GEMM: blockIdx.z selects the job (branch1 / branch2).
struct Job {
    const float* A; const float* W; const float* bias; float* C;
    const int* cntp; int K; int N;
    const int* gather; const int* scatter; int ldc;
};

__global__ __launch_bounds__(256, 2)
void k_gemm_dual(Job j0, Job j1)
{
    const Job& j = (blockIdx.z == 0) ? j0 : j1;
    int M = *j.cntp;
    int tileM = blockIdx.y * 128;
    if (tileM >= M) return;
    int tileN = blockIdx.x * 128;
    if (tileN >= j.N) return;
    gemm_tc_body<false>(j.A, j.W, j.bias, j.C, M, j.K, j.gather, j.scatter,
                        j.ldc, 0, nullptr, nullptr, tileM, tileN);
}

// ---------------------------------------------------------------------------
extern "C" void kernel_launch(void* const* d_in, const int* in_sizes, int n_in,
                              void* d_out, int out_size)
{
    const float* h       = (const float*)d_in[0];   // [4,4096,2048]
    const float* freq    = (const float*)d_in[1];   // [4,4096]
    const float* imp     = (const float*)d_in[2];   // [4,4096]
    const float* comp1_W = (const float*)d_in[3];   // [1024,2048]
    const float* comp1_b = (const float*)d_in[4];
    const float* adpt1_W = (const float*)d_in[5];   // [1024,1024]
    const float* adpt1_b = (const float*)d_in[6];
    const float* dec1_W  = (const float*)d_in[7];   // [2048,1024]
    const float* dec1_b  = (const float*)d_in[8];
    const float* comp2_W = (const float*)d_in[9];   // [512,2048]
    const float* comp2_b = (const float*)d_in[10];
    const float* adpt2_W = (const float*)d_in[11];  // [512,512]
    const float* adpt2_b = (const float*)d_in[12];
    const float* dec2_W  = (const float*)d_in[13];  // [2048,512]
    const float* dec2_b  = (const float*)d_in[14];
    const float* sel1_W  = (const float*)d_in[15];  // [512,2048]
    const float* sel1_b  = (const float*)d_in[16];
    const float* sel2_W  = (const float*)d_in[17];  // [3,512]
    const float* sel2_b  = (const float*)d_in[18];
    float* out = (float*)d_out;

    float *bufA, *bufB, *bufC, *bufD; int *idx1, *idx2, *cnt;
    cudaGetSymbolAddress((void**)&bufA, g_bufA);
    cudaGetSymbolAddress((void**)&bufB, g_bufB);
    cudaGetSymbolAddress((void**)&bufC, g_bufC);
    cudaGetSymbolAddress((void**)&bufD, g_bufD);
    cudaGetSymbolAddress((void**)&idx1, g_idx1);
    cudaGetSymbolAddress((void**)&idx2, g_idx2);
    cudaGetSymbolAddress((void**)&cnt,  g_cnt);

    cudaFuncSetAttribute(k_gemm_sel,
        cudaFuncAttributeMaxDynamicSharedMemorySize, TC_SMEM);
    cudaFuncSetAttribute(k_gemm_dual,
        cudaFuncAttributeMaxDynamicSharedMemorySize, TC_SMEM);

    const int MAXY = TOK / 128;  // 128 m-tiles

    // out = h ; counters zeroed by block 0
    {
        int n4 = TOK * HDIM / 4;
        k_prep<<<(n4 + 255) / 256, 256>>>(h, out);
    }

    // selector hidden on tensor cores, modulation fused: bufA [TOK,512]
    k_gemm_sel<<<dim3(512 / 128, MAXY), 256, TC_SMEM>>>(
        h, sel1_W, sel1_b, bufA, HDIM, 512, freq, imp);

    // tier-1: fast argmax + near-tie flagging
    k_sel_fast<<<(TOK * 32 + 255) / 256, 256>>>(bufA, sel2_W, sel2_b);

    // tier-2: exact fp32 recheck, jcol-quartered (4 CTAs/SM latency hiding)
    k_sel_exact<<<dim3(148, 4), 256>>>(h, freq, imp, sel1_W, sel1_b, sel2_W);
    k_sel_fin<<<TOK / 256, 256>>>(sel2_b);

    // build branch index lists from final decisions
    k_compact<<<(TOK + 255) / 256, 256>>>();

    // ---- both branches, pairwise-merged GEMMs (z = branch) ----
    {   // compress: b1 h->bufB [n1,1024] ; b2 h->bufC [n2,512]
        Job j0 = {h, comp1_W, comp1_b, bufB, &cnt[0], HDIM, 1024, idx1, nullptr, 1024};
        Job j1 = {h, comp2_W, comp2_b, bufC, &cnt[1], HDIM,  512, idx2, nullptr,  512};
        k_gemm_dual<<<dim3(8, MAXY, 2), 256, TC_SMEM>>>(j0, j1);
    }
    {   // adapt: b1 bufB->bufA ; b2 bufC->bufD
        Job j0 = {bufB, adpt1_W, adpt1_b, bufA, &cnt[0], 1024, 1024, nullptr, nullptr, 1024};
        Job j1 = {bufC, adpt2_W, adpt2_b, bufD, &cnt[1],  512,  512, nullptr, nullptr,  512};
        k_gemm_dual<<<dim3(8, MAXY, 2), 256, TC_SMEM>>>(j0, j1);
    }
    {   // decompress + scatter into out
        Job j0 = {bufA, dec1_W, dec1_b, out, &cnt[0], 1024, HDIM, nullptr, idx1, HDIM};
        Job j1 = {bufD, dec2_W, dec2_b, out, &cnt[1],  512, HDIM, nullptr, idx2, HDIM};
        k_gemm_dual<<<dim3(16, MAXY, 2), 256, TC_SMEM>>>(j0, j1);
    }
}

// round 12
// speedup vs baseline: 1.9494x; 1.0646x over previous
#include <cuda_runtime.h>

// Problem constants (fixed shapes from reference)
#define TOK   (4 * 4096)   // B*S = 16384 tokens
#define HDIM  2048
#define TAU   3e-3f        // tier-1 argmax-gap threshold (tf32 fast pass)
#define RTB   4            // tokens batched per recheck block
#define RQ    8            // recheck jcol split factor

// Scratch
__device__ float g_bufA[(size_t)TOK * 1024];  // branch1 stage-2
__device__ float g_bufB[(size_t)TOK * 1024];  // branch1 stage-1
__device__ float g_bufC[(size_t)TOK * 512];   // branch2 stage-1
__device__ float g_bufD[(size_t)TOK * 512];   // branch2 stage-2
__device__ float g_psel[TOK][4][3];           // fused tier-1 logit partials
__device__ float g_rpart[TOK][RQ][3];         // recheck partial logits
__device__ int   g_idx1[TOK];
__device__ int   g_idx2[TOK];
__device__ int   g_idxR[TOK];
__device__ int   g_sel[TOK];
__device__ int   g_cnt[3];   // [0]=branch1, [1]=branch2, [2]=recheck

// ---------------------------------------------------------------------------
// out = h (default for selected==0; branch scatters overwrite). Also zeroes
// the counters (block 0) so no separate init launch is needed.
__global__ void k_prep(const float* __restrict__ h, float* __restrict__ out) {
    if (blockIdx.x == 0 && threadIdx.x < 3) g_cnt[threadIdx.x] = 0;
    int i = blockIdx.x * blockDim.x + threadIdx.x;     // float4 index
    if (i < TOK * (HDIM / 4))
        ((float4*)out)[i] = ((const float4*)h)[i];
}

// ---------------------------------------------------------------------------
// Tier-1 decision from fused selector partials (fixed combine order).
// Near-ties (gap < TAU) go to the recheck list.
__global__ void k_seldec(const float* __restrict__ b2) {
    int tok = blockIdx.x * blockDim.x + threadIdx.x;
    if (tok >= TOK) return;
    float s0 = b2[0], s1 = b2[1], s2 = b2[2];
    #pragma unroll
    for (int q = 0; q < 4; q++) {
        s0 += g_psel[tok][q][0];
        s1 += g_psel[tok][q][1];
        s2 += g_psel[tok][q][2];
    }
    int sel = 0; float best = s0;             // first-max rule: strict '>'
    if (s1 > best) { best = s1; sel = 1; }
    if (s2 > best) { best = s2; sel = 2; }
    g_sel[tok] = sel;
    float m1 = fmaxf(s0, fmaxf(s1, s2));
    float mn = fminf(s0, fminf(s1, s2));
    float m2 = s0 + s1 + s2 - m1 - mn;        // second largest
    if (m1 - m2 < TAU) {
        int p = atomicAdd(&g_cnt[2], 1);
        g_idxR[p] = tok;
    }
}

// Tier-2: exact fp32 recompute, RTB tokens per block, jcols split RQ ways
// across blockIdx.y. Coalesced W1 loads; fixed-order reduces throughout.
__global__ __launch_bounds__(256)
void k_sel_exact(const float* __restrict__ h,
                 const float* __restrict__ freq,
                 const float* __restrict__ imp,
                 const float* __restrict__ W1,   // [512,2048]
                 const float* __restrict__ b1,
                 const float* __restrict__ W2)   // [3,512]
{
    __shared__ float xs[RTB][HDIM];          // 32 KB
    __shared__ float wp[8][RTB][3];          // per-warp logit partials
    const int tid  = threadIdx.x;
    const int lane = tid & 31;
    const int warp = tid >> 5;
    const int qy   = blockIdx.y;             // jcol slice 0..RQ-1
    const int nR = g_cnt[2];
    for (int base = blockIdx.x * RTB; base < nR; base += gridDim.x * RTB) {
        const int nt = min(RTB, nR - base);
        __syncthreads();                     // protect xs/wp reuse across iters
        for (int t = 0; t < nt; t++) {
            int tok = g_idxR[base + t];
            float fr = freq[tok], im = imp[tok];
            for (int k = tid; k < HDIM; k += 256) {
                float s = (k < HDIM / 2) ? fr : im;
                xs[t][k] = h[(size_t)tok * HDIM + k] * s;
            }
        }
        for (int t = nt; t < RTB; t++)
            for (int k = tid; k < HDIM; k += 256) xs[t][k] = 0.f;
        __syncthreads();

        float p[RTB][3];
        #pragma unroll
        for (int t = 0; t < RTB; t++)
            p[t][0] = p[t][1] = p[t][2] = 0.f;

        // this block: jcols [qy*64, qy*64+64); warp handles 8, 4 at a time
        #pragma unroll
        for (int grp = 0; grp < 2; grp++) {
            const int jcol0 = qy * 64 + warp * 8 + grp * 4;
            const float4* w0 = (const float4*)(W1 + (size_t)(jcol0 + 0) * HDIM);
            const float4* w1 = (const float4*)(W1 + (size_t)(jcol0 + 1) * HDIM);
            const float4* w2 = (const float4*)(W1 + (size_t)(jcol0 + 2) * HDIM);
            const float4* w3 = (const float4*)(W1 + (size_t)(jcol0 + 3) * HDIM);
            float acc[4][RTB];
            #pragma unroll
            for (int jj = 0; jj < 4; jj++)
                #pragma unroll
                for (int t = 0; t < RTB; t++) acc[jj][t] = 0.f;

            #pragma unroll 2
            for (int q = 0; q < 16; q++) {
                const int k4 = lane + q * 32;          // coalesced
                float4 wv[4] = {w0[k4], w1[k4], w2[k4], w3[k4]};
                float4 xv[RTB];
                #pragma unroll
                for (int t = 0; t < RTB; t++)
                    xv[t] = ((const float4*)xs[t])[k4];
                #pragma unroll
                for (int jj = 0; jj < 4; jj++)
                    #pragma unroll
                    for (int t = 0; t < RTB; t++)
                        acc[jj][t] = fmaf(wv[jj].x, xv[t].x,
                                     fmaf(wv[jj].y, xv[t].y,
                                     fmaf(wv[jj].z, xv[t].z,
                                     fmaf(wv[jj].w, xv[t].w, acc[jj][t]))));
            }
            // fixed shfl tree reduce
            #pragma unroll
            for (int o = 16; o; o >>= 1)
                #pragma unroll
                for (int jj = 0; jj < 4; jj++)
                    #pragma unroll
                    for (int t = 0; t < RTB; t++)
                        acc[jj][t] += __shfl_down_sync(0xffffffffu, acc[jj][t], o);
            if (lane == 0) {
                #pragma unroll
                for (int jj = 0; jj < 4; jj++) {
                    const int jcol = jcol0 + jj;
                    float bb  = b1[jcol];
                    float w20 = W2[jcol], w21 = W2[512 + jcol], w22 = W2[1024 + jcol];
                    #pragma unroll
                    for (int t = 0; t < RTB; t++) {
                        float hj = fmaxf(acc[jj][t] + bb, 0.f);
                        p[t][0] = fmaf(hj, w20, p[t][0]);
                        p[t][1] = fmaf(hj, w21, p[t][1]);
                        p[t][2] = fmaf(hj, w22, p[t][2]);
                    }
                }
            }
        }

        if (lane == 0)
            #pragma unroll
            for (int t = 0; t < RTB; t++) {
                wp[warp][t][0] = p[t][0];
                wp[warp][t][1] = p[t][1];
                wp[warp][t][2] = p[t][2];
            }
        __syncthreads();
        if (tid < nt) {
            float s0 = 0.f, s1 = 0.f, s2 = 0.f;
            #pragma unroll
            for (int w = 0; w < 8; w++) {
                s0 += wp[w][tid][0];
                s1 += wp[w][tid][1];
                s2 += wp[w][tid][2];
            }
            g_rpart[base + tid][qy][0] = s0;
            g_rpart[base + tid][qy][1] = s1;
            g_rpart[base + tid][qy][2] = s2;
        }
    }
}

// Combine the RQ jcol-slices (fixed order), decide, write g_sel.
__global__ void k_sel_fin(const float* __restrict__ b2) {
    int r = blockIdx.x * blockDim.x + threadIdx.x;
    if (r >= g_cnt[2]) return;
    float s0 = b2[0], s1 = b2[1], s2 = b2[2];
    #pragma unroll
    for (int q = 0; q < RQ; q++) {
        s0 += g_rpart[r][q][0];
        s1 += g_rpart[r][q][1];
        s2 += g_rpart[r][q][2];
    }
    int sel = 0; float best = s0;
    if (s1 > best) { best = s1; sel = 1; }
    if (s2 > best) { best = s2; sel = 2; }
    g_sel[g_idxR[r]] = sel;
}

// Build branch index lists from final g_sel.
__global__ void k_compact() {
    int tok = blockIdx.x * blockDim.x + threadIdx.x;
    if (tok >= TOK) return;
    int s = g_sel[tok];
    if (s == 1)      { int p = atomicAdd(&g_cnt[0], 1); g_idx1[p] = tok; }
    else if (s == 2) { int p = atomicAdd(&g_cnt[1], 1); g_idx2[p] = tok; }
}

// ---------------------------------------------------------------------------
// tf32 tensor-core NT GEMM, 3-stage cp.async pipeline.
// Tile 128x128, BK=32, 8 warps (2Mx4N), warp tile 64x32, mma.m16n8k8.tf32.
// Smem: 3 stages x (A 128x32 + B 128x32) fp32, XOR-swizzled (granule^row&7).
// MOD (selector): freq/imp modulation folded into A-fragment loads; epilogue
// fuses bias+ReLU+W2-dot into per-(token, n-tile) logit partials (fixed-order
// lane->warp->smem reduce) written to psel — hid never touches gmem.
// ---------------------------------------------------------------------------
__device__ __forceinline__ void mma_tf32(float (&d)[4], const unsigned (&a)[4],
                                         const unsigned (&b)[2]) {
    asm volatile(
        "mma.sync.aligned.m16n8k8.row.col.f32.tf32.tf32.f32 "
        "{%0,%1,%2,%3}, {%4,%5,%6,%7}, {%8,%9}, {%0,%1,%2,%3};\n"
        : "+f"(d[0]), "+f"(d[1]), "+f"(d[2]), "+f"(d[3])
        : "r"(a[0]), "r"(a[1]), "r"(a[2]), "r"(a[3]), "r"(b[0]), "r"(b[1]));
}

__device__ __forceinline__ void cp16(unsigned dst, const void* src, int nbytes) {
    asm volatile("cp.async.cg.shared.global [%0], [%1], 16, %2;"
                 :: "r"(dst), "l"(src), "r"(nbytes));
}

#define BK   32
#define ASZ  (128 * BK)                    // words per matrix per stage
#define STGW (2 * ASZ)                     // words per stage (A+B)
#define STGB (STGW * 4)                    // bytes per stage
#define TC_SMEM (3 * STGB)                 // 96 KB

template<bool MOD>
__device__ __forceinline__ void gemm_tc_body(
    const float* __restrict__ A, const float* __restrict__ W,
    const float* __restrict__ bias, float* __restrict__ C,
    int M, int K, const int* __restrict__ gather,
    const int* __restrict__ scatter, int ldc, int relu,
    const float* __restrict__ freq, const float* __restrict__ imp,
    const float* __restrict__ W2sel, float* __restrict__ psel,
    int tileM, int tileN)
{
    extern __shared__ float sm[];

    const int tid  = threadIdx.x;
    const int lane = tid & 31;
    const int warp = tid >> 5;
    const int wm0 = (warp >> 2) * 64;
    const int wn0 = (warp & 3) * 32;
    const int g = lane >> 2;           // 0..7
    const int c = lane & 3;            // 0..3

    // Loader mapping: granule j (16B) within row, 4 rows per thread per matrix.
    const int j  = tid & 7;
    const int r0 = tid >> 3;           // 0..31
    const float* asrc[4]; int asz[4];
    const float* bsrc[4];
    unsigned adst[4], bdst[4];
    const unsigned smb = (unsigned)__cvta_generic_to_shared(sm);
    #pragma unroll
    for (int i = 0; i < 4; i++) {
        int r = r0 + 32 * i;           // tile row 0..127
        int m = tileM + r;
        bool v = (m < M);
        int grow = v ? (gather ? gather[m] : m) : 0;
        asrc[i] = A + (size_t)grow * K + j * 4;
        asz[i]  = v ? 16 : 0;          // zfill invalid rows
        bsrc[i] = W + (size_t)(tileN + r) * K + j * 4;
        unsigned woff = r * BK + ((j ^ (r & 7)) << 2);
        adst[i] = smb + woff * 4;
        bdst[i] = smb + (ASZ + woff) * 4;
    }

    // Per-row modulation scales (selector path only; M = TOK, rows in-range).
    float sfr[4][2], sim[4][2];
    if (MOD) {
        #pragma unroll
        for (int mt = 0; mt < 4; mt++) {
            int rA = tileM + wm0 + mt * 16 + g;
            int rB = rA + 8;
            sfr[mt][0] = freq[rA]; sfr[mt][1] = freq[rB];
            sim[mt][0] = imp[rA];  sim[mt][1] = imp[rB];
        }
    }

    float acc[4][4][4];
    #pragma unroll
    for (int mt = 0; mt < 4; mt++)
        #pragma unroll
        for (int nt = 0; nt < 4; nt++)
            #pragma unroll
            for (int q = 0; q < 4; q++) acc[mt][nt][q] = 0.f;

    const int nc = K / BK;

    // Preload stages 0 and 1 (two committed groups)
    #pragma unroll
    for (int i = 0; i < 4; i++) {
        cp16(adst[i], asrc[i], asz[i]);
        cp16(bdst[i], bsrc[i], 16);
    }
    asm volatile("cp.async.commit_group;" ::: "memory");
    if (nc > 1) {
        #pragma unroll
        for (int i = 0; i < 4; i++) {
            cp16(adst[i] + STGB, asrc[i] + BK, asz[i]);
            cp16(bdst[i] + STGB, bsrc[i] + BK, 16);
        }
    }
    asm volatile("cp.async.commit_group;" ::: "memory");

    for (int ch = 0; ch < nc; ch++) {
        asm volatile("cp.async.wait_group 1;" ::: "memory");
        __syncthreads();

        if (ch + 2 < nc) {
            const int koff = (ch + 2) * BK;
            const unsigned so = ((ch + 2) % 3) * STGB;
            #pragma unroll
            for (int i = 0; i < 4; i++) {
                cp16(adst[i] + so, asrc[i] + koff, asz[i]);
                cp16(bdst[i] + so, bsrc[i] + koff, 16);
            }
        }
        asm volatile("cp.async.commit_group;" ::: "memory");

        const float* As = sm + (ch % 3) * STGW;
        const float* Bs = As + ASZ;
        const bool useFr = MOD && (ch * BK * 2 < K);   // first half of K

        #pragma unroll
        for (int ks = 0; ks < 4; ks++) {
            const int kb2 = ks * 2;            // granule index pair base
            unsigned afr[4][4];
            #pragma unroll
            for (int mt = 0; mt < 4; mt++) {
                int m = wm0 + mt * 16 + g;
                int sw = m & 7;                 // (m+8)&7 == m&7
                int q0 = (kb2 ^ sw) * 4 + c;
                int q1 = ((kb2 + 1) ^ sw) * 4 + c;
                const float* pr0 = As + m * BK;
                const float* pr1 = As + (m + 8) * BK;
                if (MOD) {
                    float s0 = useFr ? sfr[mt][0] : sim[mt][0];
                    float s1 = useFr ? sfr[mt][1] : sim[mt][1];
                    afr[mt][0] = __float_as_uint(pr0[q0] * s0);
                    afr[mt][1] = __float_as_uint(pr1[q0] * s1);
                    afr[mt][2] = __float_as_uint(pr0[q1] * s0);
                    afr[mt][3] = __float_as_uint(pr1[q1] * s1);
                } else {
                    afr[mt][0] = __float_as_uint(pr0[q0]);
                    afr[mt][1] = __float_as_uint(pr1[q0]);
                    afr[mt][2] = __float_as_uint(pr0[q1]);
                    afr[mt][3] = __float_as_uint(pr1[q1]);
                }
            }
            unsigned bfr[4][2];
            #pragma unroll
            for (int nt = 0; nt < 4; nt++) {
                int n = wn0 + nt * 8 + g;
                int sw = n & 7;
                const float* pn = Bs + n * BK;
                bfr[nt][0] = __float_as_uint(pn[(kb2 ^ sw) * 4 + c]);
                bfr[nt][1] = __float_as_uint(pn[((kb2 + 1) ^ sw) * 4 + c]);
            }
            #pragma unroll
            for (int mt = 0; mt < 4; mt++)
                #pragma unroll
                for (int nt = 0; nt < 4; nt++)
                    mma_tf32(acc[mt][nt], afr[mt], bfr[nt]);
        }
    }

    if (MOD) {
        // Fused selector epilogue: partial logits for this n-tile.
        __syncthreads();                 // smem free for reuse
        float* part = sm;                // [warpN=4][128 rows][3]
        float w2v[3][8], bbv[8];
        #pragma unroll
        for (int nt = 0; nt < 4; nt++)
            #pragma unroll
            for (int cc = 0; cc < 2; cc++) {
                int col = tileN + wn0 + nt * 8 + c * 2 + cc;
                bbv[nt * 2 + cc]    = bias[col];
                w2v[0][nt * 2 + cc] = W2sel[col];
                w2v[1][nt * 2 + cc] = W2sel[512 + col];
                w2v[2][nt * 2 + cc] = W2sel[1024 + col];
            }
        #pragma unroll
        for (int mt = 0; mt < 4; mt++)
            #pragma unroll
            for (int h2 = 0; h2 < 2; h2++) {
                int r = wm0 + mt * 16 + g + 8 * h2;
                float l0 = 0.f, l1 = 0.f, l2 = 0.f;
                #pragma unroll
                for (int nt = 0; nt < 4; nt++)
                    #pragma unroll
                    for (int cc = 0; cc < 2; cc++) {
                        float v = fmaxf(acc[mt][nt][2 * h2 + cc] + bbv[nt * 2 + cc], 0.f);
                        l0 = fmaf(v, w2v[0][nt * 2 + cc], l0);
                        l1 = fmaf(v, w2v[1][nt * 2 + cc], l1);
                        l2 = fmaf(v, w2v[2][nt * 2 + cc], l2);
                    }
                // fixed reduce over the 4 c-lanes (segment width 4)
                l0 += __shfl_down_sync(0xffffffffu, l0, 2, 4);
                l1 += __shfl_down_sync(0xffffffffu, l1, 2, 4);
                l2 += __shfl_down_sync(0xffffffffu, l2, 2, 4);
                l0 += __shfl_down_sync(0xffffffffu, l0, 1, 4);
                l1 += __shfl_down_sync(0xffffffffu, l1, 1, 4);
                l2 += __shfl_down_sync(0xffffffffu, l2, 1, 4);
                if (c == 0) {
                    float* pr = part + ((size_t)(warp & 3) * 128 + r) * 3;
                    pr[0] = l0; pr[1] = l1; pr[2] = l2;
                }
            }
        __syncthreads();
        if (tid < 128) {
            float s0 = 0.f, s1 = 0.f, s2 = 0.f;
            #pragma unroll
            for (int w = 0; w < 4; w++) {   // fixed order over warpN
                const float* pr = part + ((size_t)w * 128 + tid) * 3;
                s0 += pr[0]; s1 += pr[1]; s2 += pr[2];
            }
            float* dst = psel + ((size_t)(tileM + tid) * 4 + blockIdx.x) * 3;
            dst[0] = s0; dst[1] = s1; dst[2] = s2;
        }
        return;
    }

    // Epilogue: bias, optional ReLU, optional row scatter. float2 stores.
    #pragma unroll
    for (int mt = 0; mt < 4; mt++) {
        int rowA = tileM + wm0 + mt * 16 + g;
        #pragma unroll
        for (int h2 = 0; h2 < 2; h2++) {
            int r = rowA + 8 * h2;
            if (r >= M) continue;
            int cr = scatter ? scatter[r] : r;
            float* crow = C + (size_t)cr * ldc;
            #pragma unroll
            for (int nt = 0; nt < 4; nt++) {
                int col = tileN + wn0 + nt * 8 + c * 2;
                float2 bb = *(const float2*)(bias + col);
                float2 o;
                o.x = acc[mt][nt][2 * h2 + 0] + bb.x;
                o.y = acc[mt][nt][2 * h2 + 1] + bb.y;
                if (relu) { o.x = fmaxf(o.x, 0.f); o.y = fmaxf(o.y, 0.f); }
                *(float2*)(crow + col) = o;
            }
        }
    }
}

// Selector GEMM: modulation + fused logit partials. Static M = TOK.
__global__ __launch_bounds__(256, 2)
void k_gemm_sel(const float* __restrict__ A, const float* __restrict__ W,
                const float* __restrict__ bias,
                const float* __restrict__ freq, const float* __restrict__ imp,
                const float* __restrict__ W2)
{
    gemm_tc_body<true>(A, W, bias, nullptr, TOK, HDIM, nullptr, nullptr, 0, 1,
                       freq, imp, W2, &g_psel[0][0][0],
                       blockIdx.y * 128, blockIdx.x * 128);
}

// Dual-branch GEMM: blockIdx.z selects the job (branch1 / branch2).
struct Job {
    const float* A; const float* W; const float* bias; float* C;
    const int* cntp; int K; int N;
    const int* gather; const int* scatter; int ldc;
};

__global__ __launch_bounds__(256, 2)
void k_gemm_dual(Job j0, Job j1)
{
    const Job& j = (blockIdx.z == 0) ? j0 : j1;
    int M = *j.cntp;
    int tileM = blockIdx.y * 128;
    if (tileM >= M) return;
    int tileN = blockIdx.x * 128;
    if (tileN >= j.N) return;
    gemm_tc_body<false>(j.A, j.W, j.bias, j.C, M, j.K, j.gather, j.scatter,
                        j.ldc, 0, nullptr, nullptr, nullptr, nullptr,
                        tileM, tileN);
}

// ---------------------------------------------------------------------------
extern "C" void kernel_launch(void* const* d_in, const int* in_sizes, int n_in,
                              void* d_out, int out_size)
{
    const float* h       = (const float*)d_in[0];   // [4,4096,2048]
    const float* freq    = (const float*)d_in[1];   // [4,4096]
    const float* imp     = (const float*)d_in[2];   // [4,4096]
    const float* comp1_W = (const float*)d_in[3];   // [1024,2048]
    const float* comp1_b = (const float*)d_in[4];
    const float* adpt1_W = (const float*)d_in[5];   // [1024,1024]
    const float* adpt1_b = (const float*)d_in[6];
    const float* dec1_W  = (const float*)d_in[7];   // [2048,1024]
    const float* dec1_b  = (const float*)d_in[8];
    const float* comp2_W = (const float*)d_in[9];   // [512,2048]
    const float* comp2_b = (const float*)d_in[10];
    const float* adpt2_W = (const float*)d_in[11];  // [512,512]
    const float* adpt2_b = (const float*)d_in[12];
    const float* dec2_W  = (const float*)d_in[13];  // [2048,512]
    const float* dec2_b  = (const float*)d_in[14];
    const float* sel1_W  = (const float*)d_in[15];  // [512,2048]
    const float* sel1_b  = (const float*)d_in[16];
    const float* sel2_W  = (const float*)d_in[17];  // [3,512]
    const float* sel2_b  = (const float*)d_in[18];
    float* out = (float*)d_out;

    float *bufA, *bufB, *bufC, *bufD; int *idx1, *idx2, *cnt;
    cudaGetSymbolAddress((void**)&bufA, g_bufA);
    cudaGetSymbolAddress((void**)&bufB, g_bufB);
    cudaGetSymbolAddress((void**)&bufC, g_bufC);
    cudaGetSymbolAddress((void**)&bufD, g_bufD);
    cudaGetSymbolAddress((void**)&idx1, g_idx1);
    cudaGetSymbolAddress((void**)&idx2, g_idx2);
    cudaGetSymbolAddress((void**)&cnt,  g_cnt);

    cudaFuncSetAttribute(k_gemm_sel,
        cudaFuncAttributeMaxDynamicSharedMemorySize, TC_SMEM);
    cudaFuncSetAttribute(k_gemm_dual,
        cudaFuncAttributeMaxDynamicSharedMemorySize, TC_SMEM);

    const int MAXY = TOK / 128;  // 128 m-tiles

    // out = h ; counters zeroed by block 0
    {
        int n4 = TOK * HDIM / 4;
        k_prep<<<(n4 + 255) / 256, 256>>>(h, out);
    }

    // selector: tensor-core GEMM with fused tier-1 logit partials
    k_gemm_sel<<<dim3(512 / 128, MAXY), 256, TC_SMEM>>>(
        h, sel1_W, sel1_b, freq, imp, sel2_W);

    // tier-1 decision + near-tie flagging (fixed-order partial combine)
    k_seldec<<<TOK / 256, 256>>>(sel2_b);

    // tier-2: exact fp32 recheck, RQ-way jcol split
    k_sel_exact<<<dim3(148, RQ), 256>>>(h, freq, imp, sel1_W, sel1_b, sel2_W);
    k_sel_fin<<<TOK / 256, 256>>>(sel2_b);

    // build branch index lists from final decisions
    k_compact<<<(TOK + 255) / 256, 256>>>();

    // ---- both branches, pairwise-merged GEMMs (z = branch) ----
    {   // compress: b1 h->bufB [n1,1024] ; b2 h->bufC [n2,512]
        Job j0 = {h, comp1_W, comp1_b, bufB, &cnt[0], HDIM, 1024, idx1, nullptr, 1024};
        Job j1 = {h, comp2_W, comp2_b, bufC, &cnt[1], HDIM,  512, idx2, nullptr,  512};
        k_gemm_dual<<<dim3(8, MAXY, 2), 256, TC_SMEM>>>(j0, j1);
    }
    {   // adapt: b1 bufB->bufA ; b2 bufC->bufD
        Job j0 = {bufB, adpt1_W, adpt1_b, bufA, &cnt[0], 1024, 1024, nullptr, nullptr, 1024};
        Job j1 = {bufC, adpt2_W, adpt2_b, bufD, &cnt[1],  512,  512, nullptr, nullptr,  512};
        k_gemm_dual<<<dim3(8, MAXY, 2), 256, TC_SMEM>>>(j0, j1);
    }
    {   // decompress + scatter into out
        Job j0 = {bufA, dec1_W, dec1_b, out, &cnt[0], 1024, HDIM, nullptr, idx1, HDIM};
        Job j1 = {bufD, dec2_W, dec2_b, out, &cnt[1],  512, HDIM, nullptr, idx2, HDIM};
        k_gemm_dual<<<dim3(16, MAXY, 2), 256, TC_SMEM>>>(j0, j1);
    }
}